// round 4
// baseline (speedup 1.0000x reference)
#include <cuda_runtime.h>
#include <cstdint>

#define BATCH 8
#define NTOK 4096
#define NLAT 64
#define NKEYS 4160
#define DMODEL 1024
#define HEADS 16
#define DH 64

// ---------------- scratch (static device memory; no allocations) ----------------
__device__ float g_ln [(size_t)BATCH * NKEYS * DMODEL];        // concat(LN(x), LN(lat)) per batch
__device__ float g_kv [(size_t)BATCH * NKEYS * 2 * DMODEL];    // [b, key, 2048] : k | v
__device__ float g_q  [(size_t)BATCH * NLAT * DMODEL];         // (512, 1024)
__device__ float g_att[(size_t)BATCH * NLAT * DMODEL];         // (512, 1024)

// ---------------- LayerNorm ----------------
__global__ __launch_bounds__(256) void ln_kernel(
    const float* __restrict__ in, const float* __restrict__ gamma,
    const float* __restrict__ beta, float* __restrict__ out,
    int in_rpb, int out_off)
{
    const int row = blockIdx.x;
    const int b = row / in_rpb;
    const int r = row - b * in_rpb;
    const int t = threadIdx.x;
    const float* xr = in + (size_t)row * DMODEL;
    float4 v = ((const float4*)xr)[t];
    float s  = v.x + v.y + v.z + v.w;
    float ss = v.x*v.x + v.y*v.y + v.z*v.z + v.w*v.w;
#pragma unroll
    for (int o = 16; o; o >>= 1) {
        s  += __shfl_xor_sync(0xffffffffu, s, o);
        ss += __shfl_xor_sync(0xffffffffu, ss, o);
    }
    __shared__ float rs[8], rss[8];
    if ((t & 31) == 0) { rs[t >> 5] = s; rss[t >> 5] = ss; }
    __syncthreads();
    float sum = 0.f, sq = 0.f;
#pragma unroll
    for (int i = 0; i < 8; i++) { sum += rs[i]; sq += rss[i]; }
    const float mu  = sum * (1.f / DMODEL);
    const float inv = rsqrtf(sq * (1.f / DMODEL) - mu * mu + 1e-5f);
    float4 g  = ((const float4*)gamma)[t];
    float4 bb = ((const float4*)beta)[t];
    float4 o;
    o.x = (v.x - mu) * inv * g.x + bb.x;
    o.y = (v.y - mu) * inv * g.y + bb.y;
    o.z = (v.z - mu) * inv * g.z + bb.z;
    o.w = (v.w - mu) * inv * g.w + bb.w;
    ((float4*)(out + ((size_t)(b * NKEYS + out_off + r)) * DMODEL))[t] = o;
}

// ---------------- tf32 GEMM: C(MxN) = A(MxK) @ B(KxN), all row-major ----------------
#define BM 128
#define BN 128
#define BK 32
#define SLDA 36     // BK + 4  -> conflict-free A-fragment LDS
#define SLDB 136    // BN + 8  -> conflict-free B-fragment LDS
#define A_STAGE (BM * SLDA)   // 4608 floats
#define B_STAGE (BK * SLDB)   // 4352 floats
#define GEMM_SMEM ((2 * A_STAGE + 2 * B_STAGE) * 4)   // 71680 B

__device__ __forceinline__ void cp_async16(uint32_t s, const void* g) {
    asm volatile("cp.async.cg.shared.global [%0], [%1], 16;\n" :: "r"(s), "l"(g));
}
__device__ __forceinline__ void cp_commit() { asm volatile("cp.async.commit_group;\n" ::); }
__device__ __forceinline__ void cp_wait0()  { asm volatile("cp.async.wait_group 0;\n" ::); }
__device__ __forceinline__ void cp_wait1()  { asm volatile("cp.async.wait_group 1;\n" ::); }

__device__ __forceinline__ uint32_t f2tf32(float f) {
    uint32_t r; asm volatile("cvt.rna.tf32.f32 %0, %1;\n" : "=r"(r) : "f"(f)); return r;
}

__device__ __forceinline__ void mma8(float* d, const uint32_t* a, const uint32_t* b) {
    asm volatile(
        "mma.sync.aligned.m16n8k8.row.col.f32.tf32.tf32.f32 "
        "{%0,%1,%2,%3}, {%4,%5,%6,%7}, {%8,%9}, {%0,%1,%2,%3};\n"
        : "+f"(d[0]), "+f"(d[1]), "+f"(d[2]), "+f"(d[3])
        : "r"(a[0]), "r"(a[1]), "r"(a[2]), "r"(a[3]), "r"(b[0]), "r"(b[1]));
}

// A-row remap: global_row -> (row>>ashift)*abstride + (row&mask)*K  (handles the
// per-batch strided latent rows for the q GEMM; ashift=31 => flat).
__global__ __launch_bounds__(256) void gemm_tf32(
    const float* __restrict__ A, const float* __restrict__ B, float* __restrict__ C,
    int M, int N, int K, int ashift, long long abstride)
{
    extern __shared__ float sm[];
    float* As0 = sm;
    float* Bs0 = sm + 2 * A_STAGE;
    const int tid  = threadIdx.x;
    const int bm   = blockIdx.y * BM;
    const int bn   = blockIdx.x * BN;
    const int warp = tid >> 5, lane = tid & 31;
    const int wm = (warp >> 1) * 32, wn = (warp & 1) * 64;
    const int g4 = lane >> 2, t4 = lane & 3;
    const unsigned amask = (1u << ashift) - 1u;

    uint32_t sa_base = (uint32_t)__cvta_generic_to_shared(As0);
    uint32_t sb_base = (uint32_t)__cvta_generic_to_shared(Bs0);

    long long aoff[4], boff[4];
    uint32_t  sa_addr[4], sb_addr[4];
#pragma unroll
    for (int j = 0; j < 4; j++) {
        int f = tid + j * 256;
        int r = f >> 3;
        int grow = bm + r;
        aoff[j] = (long long)(grow >> ashift) * abstride
                + (long long)((unsigned)grow & amask) * K + (f & 7) * 4;
        sa_addr[j] = sa_base + (uint32_t)((r * SLDA + (f & 7) * 4) * 4);
        int rb = f >> 5;
        boff[j] = (long long)rb * N + bn + (f & 31) * 4;
        sb_addr[j] = sb_base + (uint32_t)((rb * SLDB + (f & 31) * 4) * 4);
    }

    float acc[2][8][4];
#pragma unroll
    for (int mi = 0; mi < 2; mi++)
#pragma unroll
        for (int ni = 0; ni < 8; ni++)
#pragma unroll
            for (int c = 0; c < 4; c++) acc[mi][ni][c] = 0.f;

    auto load_stage = [&](int st, int k0) {
#pragma unroll
        for (int j = 0; j < 4; j++)
            cp_async16(sa_addr[j] + (uint32_t)(st * A_STAGE * 4), A + aoff[j] + k0);
#pragma unroll
        for (int j = 0; j < 4; j++)
            cp_async16(sb_addr[j] + (uint32_t)(st * B_STAGE * 4), B + boff[j] + (long long)k0 * N);
        cp_commit();
    };

    load_stage(0, 0);
    const int KT = K / BK;
    for (int kt = 0; kt < KT; kt++) {
        if (kt + 1 < KT) { load_stage((kt + 1) & 1, (kt + 1) * BK); cp_wait1(); }
        else             { cp_wait0(); }
        __syncthreads();
        const float* as = As0 + (kt & 1) * A_STAGE;
        const float* bs = Bs0 + (kt & 1) * B_STAGE;
#pragma unroll
        for (int kk = 0; kk < 4; kk++) {
            uint32_t af[2][4];
#pragma unroll
            for (int mi = 0; mi < 2; mi++) {
                const float* ap = as + (wm + mi * 16 + g4) * SLDA + kk * 8 + t4;
                af[mi][0] = f2tf32(ap[0]);
                af[mi][1] = f2tf32(ap[8 * SLDA]);
                af[mi][2] = f2tf32(ap[4]);
                af[mi][3] = f2tf32(ap[8 * SLDA + 4]);
            }
            uint32_t bf[8][2];
#pragma unroll
            for (int ni = 0; ni < 8; ni++) {
                const float* bp = bs + (kk * 8 + t4) * SLDB + wn + ni * 8 + g4;
                bf[ni][0] = f2tf32(bp[0]);
                bf[ni][1] = f2tf32(bp[4 * SLDB]);
            }
#pragma unroll
            for (int mi = 0; mi < 2; mi++)
#pragma unroll
                for (int ni = 0; ni < 8; ni++)
                    mma8(acc[mi][ni], af[mi], bf[ni]);
        }
        __syncthreads();
    }

#pragma unroll
    for (int mi = 0; mi < 2; mi++) {
        int r0 = bm + wm + mi * 16 + g4;
#pragma unroll
        for (int ni = 0; ni < 8; ni++) {
            int c0 = bn + wn + ni * 8 + t4 * 2;
            *(float2*)(C + (long long)r0 * N + c0)       = make_float2(acc[mi][ni][0], acc[mi][ni][1]);
            *(float2*)(C + (long long)(r0 + 8) * N + c0) = make_float2(acc[mi][ni][2], acc[mi][ni][3]);
        }
    }
}

// ---------------- flash attention, one CTA per (b, h) ----------------
// 256 threads: thread = (q = tid>>2, sub = tid&3).
// S phase: thread computes scores for keys j = 4*jj + sub (jj = 0..15).
// PV phase: thread owns out dims d = 16*d4 + 4*sub + e (d4 = 0..3, e = 0..3).
#define ATTN_SMEM ((3 * 64 * 68 + 64 * 65 + 64) * 4)   // 69120 B

__global__ __launch_bounds__(256) void attn_kernel(
    const float* __restrict__ qb, const float* __restrict__ kv,
    const int* __restrict__ mask, float* __restrict__ att)
{
    extern __shared__ float sh[];
    float* Qs = sh;                 // [64][68]
    float* Ks = Qs + 64 * 68;       // [64][68]
    float* Vs = Ks + 64 * 68;       // [64][68]
    float* Ps = Vs + 64 * 68;       // [64][65]
    float* Mk = Ps + 64 * 65;       // [64]

    const int tid = threadIdx.x;
    const int bh = blockIdx.x;
    const int b = bh >> 4, h = bh & (HEADS - 1);
    const int q = tid >> 2, sub = tid & 3;

    // load Q tile, folding the full (dh^-0.25)^2 = 1/8 scale into Q
#pragma unroll
    for (int j = 0; j < 4; j++) {
        int f = tid + j * 256;
        int r = f >> 4, c4 = f & 15;
        float4 v = *(const float4*)(qb + ((size_t)(b * NLAT + r)) * DMODEL + h * DH + c4 * 4);
        v.x *= 0.125f; v.y *= 0.125f; v.z *= 0.125f; v.w *= 0.125f;
        *(float4*)(Qs + r * 68 + c4 * 4) = v;
    }

    float4 Oa[4];
#pragma unroll
    for (int i = 0; i < 4; i++) Oa[i] = make_float4(0.f, 0.f, 0.f, 0.f);
    float mrun = -1e30f, lsum = 0.f;

    const float* kbase = kv + ((size_t)b * NKEYS) * 2048 + h * DH;

    for (int ch = 0; ch < NKEYS / 64; ch++) {
        const int j0 = ch * 64;
        __syncthreads();
        // stage K and V chunks (row stride 2048 floats; 256B contiguous per row)
#pragma unroll
        for (int j = 0; j < 4; j++) {
            int f = tid + j * 256;
            int r = f >> 4, c4 = f & 15;
            const float* rp = kbase + (size_t)(j0 + r) * 2048 + c4 * 4;
            *(float4*)(Ks + r * 68 + c4 * 4) = *(const float4*)rp;
            *(float4*)(Vs + r * 68 + c4 * 4) = *(const float4*)(rp + DMODEL);
        }
        if (tid < 64)
            Mk[tid] = (ch < 64) ? ((mask[(size_t)b * NTOK + j0 + tid] != 0) ? 1.f : 0.f) : 1.f;
        __syncthreads();

        // ---- scores ----
        float sreg[16];
#pragma unroll
        for (int jj = 0; jj < 16; jj++) sreg[jj] = 0.f;
#pragma unroll
        for (int d4 = 0; d4 < 16; d4++) {
            float4 qv = *(const float4*)(Qs + q * 68 + d4 * 4);
#pragma unroll
            for (int jj = 0; jj < 16; jj++) {
                float4 kvv = *(const float4*)(Ks + (4 * jj + sub) * 68 + d4 * 4);
                sreg[jj] += qv.x * kvv.x + qv.y * kvv.y + qv.z * kvv.z + qv.w * kvv.w;
            }
        }
#pragma unroll
        for (int jj = 0; jj < 16; jj++)
            if (!(Mk[4 * jj + sub] > 0.f)) sreg[jj] = -1e30f;

        // ---- online softmax ----
        float mloc = -1e30f;
#pragma unroll
        for (int jj = 0; jj < 16; jj++) mloc = fmaxf(mloc, sreg[jj]);
        mloc = fmaxf(mloc, __shfl_xor_sync(0xffffffffu, mloc, 1));
        mloc = fmaxf(mloc, __shfl_xor_sync(0xffffffffu, mloc, 2));
        float mnew = fmaxf(mrun, mloc);
        float corr = __expf(mrun - mnew);
        float psum = 0.f;
#pragma unroll
        for (int jj = 0; jj < 16; jj++) {
            int j = 4 * jj + sub;
            float p = __expf(sreg[jj] - mnew) * Mk[j];  // Mk=0 kills masked even when mnew==-1e30
            psum += p;
            Ps[q * 65 + j] = p;
        }
        psum += __shfl_xor_sync(0xffffffffu, psum, 1);
        psum += __shfl_xor_sync(0xffffffffu, psum, 2);
        lsum = lsum * corr + psum;
#pragma unroll
        for (int i = 0; i < 4; i++) { Oa[i].x *= corr; Oa[i].y *= corr; Oa[i].z *= corr; Oa[i].w *= corr; }
        mrun = mnew;
        __syncthreads();

        // ---- P @ V ----
#pragma unroll 4
        for (int j = 0; j < 64; j++) {
            float p = Ps[q * 65 + j];
#pragma unroll
            for (int d4 = 0; d4 < 4; d4++) {
                float4 v = *(const float4*)(Vs + j * 68 + d4 * 16 + sub * 4);
                Oa[d4].x += p * v.x; Oa[d4].y += p * v.y;
                Oa[d4].z += p * v.z; Oa[d4].w += p * v.w;
            }
        }
    }

    float rl = __fdividef(1.f, lsum);
    float* orow = att + ((size_t)(b * NLAT + q)) * DMODEL + h * DH;
#pragma unroll
    for (int d4 = 0; d4 < 4; d4++) {
        float4 v = Oa[d4];
        v.x *= rl; v.y *= rl; v.z *= rl; v.w *= rl;
        *(float4*)(orow + d4 * 16 + sub * 4) = v;
    }
}

// ---------------- launch ----------------
extern "C" void kernel_launch(void* const* d_in, const int* in_sizes, int n_in,
                              void* d_out, int out_size)
{
    const float* x    = (const float*)d_in[0];
    const float* lat  = (const float*)d_in[1];
    const int*   mask = (const int*)d_in[2];
    const float* g1   = (const float*)d_in[3];
    const float* b1   = (const float*)d_in[4];
    const float* g2   = (const float*)d_in[5];
    const float* b2   = (const float*)d_in[6];
    const float* Wq   = (const float*)d_in[7];
    const float* Wkv  = (const float*)d_in[8];
    const float* Wout = (const float*)d_in[9];
    float* out = (float*)d_out;

    float *ln, *kvp, *qp, *attp;
    cudaGetSymbolAddress((void**)&ln,   g_ln);
    cudaGetSymbolAddress((void**)&kvp,  g_kv);
    cudaGetSymbolAddress((void**)&qp,   g_q);
    cudaGetSymbolAddress((void**)&attp, g_att);

    cudaFuncSetAttribute(gemm_tf32,   cudaFuncAttributeMaxDynamicSharedMemorySize, GEMM_SMEM);
    cudaFuncSetAttribute(attn_kernel, cudaFuncAttributeMaxDynamicSharedMemorySize, ATTN_SMEM);

    // LayerNorms into the concatenated buffer
    ln_kernel<<<BATCH * NTOK, 256>>>(x,   g1, b1, ln, NTOK, 0);
    ln_kernel<<<BATCH * NLAT, 256>>>(lat, g2, b2, ln, NLAT, NTOK);

    // kv = ln_concat @ Wkv : (33280 x 1024) @ (1024 x 2048)
    gemm_tf32<<<dim3(2048 / BN, (BATCH * NKEYS) / BM), 256, GEMM_SMEM>>>(
        ln, Wkv, kvp, BATCH * NKEYS, 2048, DMODEL, 31, 0LL);

    // q = ln_lat @ Wq : rows strided per batch inside ln_concat
    gemm_tf32<<<dim3(1024 / BN, (BATCH * NLAT) / BM), 256, GEMM_SMEM>>>(
        ln + (size_t)NTOK * DMODEL, Wq, qp, BATCH * NLAT, DMODEL, DMODEL,
        6, (long long)NKEYS * DMODEL);

    // attention
    attn_kernel<<<BATCH * HEADS, 256, ATTN_SMEM>>>(qp, kvp, mask, attp);

    // out = att @ Wout
    gemm_tf32<<<dim3(1024 / BN, (BATCH * NLAT) / BM), 256, GEMM_SMEM>>>(
        attp, Wout, out, BATCH * NLAT, DMODEL, DMODEL, 31, 0LL);
}

// round 8
// speedup vs baseline: 1.7930x; 1.7930x over previous
#include <cuda_runtime.h>
#include <cstdint>

#define BATCH 8
#define NTOK 4096
#define NLAT 64
#define PADK 4224              // padded compacted-key capacity per batch (33 * 128)
#define DMODEL 1024
#define HEADS 16
#define DH 64

// ---------------- scratch (static device memory; no allocations) ----------------
__device__ float g_ln   [(size_t)BATCH * PADK * DMODEL];       // LN rows in compacted key order
__device__ float g_kv   [(size_t)BATCH * PADK * 2 * DMODEL];   // [b, slot, 2048] : k | v
__device__ float g_lnlat[(size_t)BATCH * NLAT * DMODEL];       // dense LN(latents) for q GEMM
__device__ float g_q    [(size_t)BATCH * NLAT * DMODEL];
__device__ float g_att  [(size_t)BATCH * NLAT * DMODEL];
__device__ int   g_idx  [(size_t)BATCH * PADK];                // compacted source-row indices
__device__ int   g_cnt  [BATCH];                               // nk[b] = #unmasked + 64

// ---------------- helpers ----------------
__device__ __forceinline__ uint32_t smem_u32(const void* p) {
    uint32_t a;
    asm("{ .reg .u64 t; cvta.to.shared.u64 t, %1; cvt.u32.u64 %0, t; }" : "=r"(a) : "l"(p));
    return a;
}
__device__ __forceinline__ void cp_async16(uint32_t s, const void* g) {
    asm volatile("cp.async.cg.shared.global [%0], [%1], 16;\n" :: "r"(s), "l"(g));
}
__device__ __forceinline__ void cp_commit() { asm volatile("cp.async.commit_group;\n" ::); }
__device__ __forceinline__ void cp_wait0()  { asm volatile("cp.async.wait_group 0;\n" ::); }
__device__ __forceinline__ void cp_wait1()  { asm volatile("cp.async.wait_group 1;\n" ::); }

__device__ __forceinline__ uint32_t f2tf32(float f) {
    uint32_t r; asm volatile("cvt.rna.tf32.f32 %0, %1;\n" : "=r"(r) : "f"(f)); return r;
}
__device__ __forceinline__ void mma8(float* d, const uint32_t* a, const uint32_t* b) {
    asm volatile(
        "mma.sync.aligned.m16n8k8.row.col.f32.tf32.tf32.f32 "
        "{%0,%1,%2,%3}, {%4,%5,%6,%7}, {%8,%9}, {%0,%1,%2,%3};\n"
        : "+f"(d[0]), "+f"(d[1]), "+f"(d[2]), "+f"(d[3])
        : "r"(a[0]), "r"(a[1]), "r"(a[2]), "r"(a[3]), "r"(b[0]), "r"(b[1]));
}

// ---------------- mask compaction: deterministic block prefix-sum ----------------
__global__ __launch_bounds__(1024) void compact_kernel(
    const int* __restrict__ mask, int* __restrict__ idx, int* __restrict__ cnt)
{
    __shared__ int wsum[32];
    __shared__ int stotal;
    const int b = blockIdx.x, t = threadIdx.x;
    const int* mb = mask + (size_t)b * NTOK;
    const int base4 = t * 4;
    int m0 = mb[base4 + 0] != 0, m1 = mb[base4 + 1] != 0;
    int m2 = mb[base4 + 2] != 0, m3 = mb[base4 + 3] != 0;
    const int s = m0 + m1 + m2 + m3;
    const int lane = t & 31, w = t >> 5;
    int inc = s;
#pragma unroll
    for (int o = 1; o < 32; o <<= 1) {
        int v = __shfl_up_sync(0xffffffffu, inc, o);
        if (lane >= o) inc += v;
    }
    if (lane == 31) wsum[w] = inc;
    __syncthreads();
    if (w == 0) {
        int v = wsum[lane];
#pragma unroll
        for (int o = 1; o < 32; o <<= 1) {
            int u = __shfl_up_sync(0xffffffffu, v, o);
            if (lane >= o) v += u;
        }
        wsum[lane] = v;
    }
    __syncthreads();
    const int basep = inc - s + (w ? wsum[w - 1] : 0);   // exclusive prefix
    int* ib = idx + (size_t)b * PADK;
    int p = basep;
    if (m0) ib[p++] = base4 + 0;
    if (m1) ib[p++] = base4 + 1;
    if (m2) ib[p++] = base4 + 2;
    if (m3) ib[p++] = base4 + 3;
    if (t == 1023) stotal = basep + s;
    __syncthreads();
    const int total = stotal;
    if (t < NLAT) ib[total + t] = NTOK + t;              // latents always valid
    for (int j = total + NLAT + t; j < PADK; j += 1024) ib[j] = NTOK;  // pad -> latent 0
    if (t == 0) cnt[b] = total + NLAT;
}

// ---------------- shared LN row body (256 threads, 4 floats/thread) ----------------
__device__ __forceinline__ void ln_row(const float* __restrict__ xr,
                                       const float* __restrict__ gamma,
                                       const float* __restrict__ beta,
                                       float* __restrict__ outr)
{
    const int t = threadIdx.x;
    float4 v = ((const float4*)xr)[t];
    float s  = v.x + v.y + v.z + v.w;
    float ss = v.x*v.x + v.y*v.y + v.z*v.z + v.w*v.w;
#pragma unroll
    for (int o = 16; o; o >>= 1) {
        s  += __shfl_xor_sync(0xffffffffu, s, o);
        ss += __shfl_xor_sync(0xffffffffu, ss, o);
    }
    __shared__ float rs[8], rss[8];
    if ((t & 31) == 0) { rs[t >> 5] = s; rss[t >> 5] = ss; }
    __syncthreads();
    float sum = 0.f, sq = 0.f;
#pragma unroll
    for (int i = 0; i < 8; i++) { sum += rs[i]; sq += rss[i]; }
    const float mu  = sum * (1.f / DMODEL);
    const float inv = rsqrtf(sq * (1.f / DMODEL) - mu * mu + 1e-5f);
    float4 g  = ((const float4*)gamma)[t];
    float4 bb = ((const float4*)beta)[t];
    float4 o;
    o.x = (v.x - mu) * inv * g.x + bb.x;
    o.y = (v.y - mu) * inv * g.y + bb.y;
    o.z = (v.z - mu) * inv * g.z + bb.z;
    o.w = (v.w - mu) * inv * g.w + bb.w;
    ((float4*)outr)[t] = o;
}

// LN of latents, dense (for q GEMM). grid = BATCH*NLAT rows.
__global__ __launch_bounds__(256) void ln_dense(
    const float* __restrict__ in, const float* __restrict__ gamma,
    const float* __restrict__ beta, float* __restrict__ out)
{
    const size_t row = blockIdx.x;
    ln_row(in + row * DMODEL, gamma, beta, out + row * DMODEL);
}

// LN in compacted order. grid = (PADK, BATCH); early-exit beyond ceil128(nk).
__global__ __launch_bounds__(256) void ln_gather(
    const float* __restrict__ x, const float* __restrict__ lat,
    const int* __restrict__ idx, const int* __restrict__ cnt,
    const float* __restrict__ g1, const float* __restrict__ b1,
    const float* __restrict__ g2, const float* __restrict__ b2,
    float* __restrict__ out)
{
    const int b = blockIdx.y;
    const int slot = blockIdx.x;
    const int nk = cnt[b];
    if (slot >= ((nk + 127) & ~127)) return;      // only rows GEMM tiles will touch
    const int g = idx[(size_t)b * PADK + slot];
    const float* src;
    const float *gam, *bet;
    if (g < NTOK) { src = x   + ((size_t)b * NTOK + g) * DMODEL;          gam = g1; bet = b1; }
    else          { src = lat + ((size_t)b * NLAT + (g - NTOK)) * DMODEL; gam = g2; bet = b2; }
    ln_row(src, gam, bet, out + ((size_t)b * PADK + slot) * DMODEL);
}

// ---------------- tf32 mma.sync GEMM (proven R4 core) ----------------
#define BM 128
#define BN 128
#define BK 32
#define SLDA 36
#define SLDB 136
#define A_STAGE (BM * SLDA)
#define B_STAGE (BK * SLDB)
#define GEMM_SMEM ((2 * A_STAGE + 2 * B_STAGE) * 4)

// Shared inner body: A at abase (row-major, lda=K), B row-major K x N, C at cbase.
__device__ __forceinline__ void gemm_body(
    const float* __restrict__ A, const float* __restrict__ B, float* __restrict__ C,
    int N, int K, int bn)
{
    extern __shared__ float sm[];
    float* As0 = sm;
    float* Bs0 = sm + 2 * A_STAGE;
    const int tid  = threadIdx.x;
    const int warp = tid >> 5, lane = tid & 31;
    const int wm = (warp >> 1) * 32, wn = (warp & 1) * 64;
    const int g4 = lane >> 2, t4 = lane & 3;

    uint32_t sa_base = smem_u32(As0);
    uint32_t sb_base = smem_u32(Bs0);

    long long aoff[4], boff[4];
    uint32_t  sa_addr[4], sb_addr[4];
#pragma unroll
    for (int j = 0; j < 4; j++) {
        int f = tid + j * 256;
        int r = f >> 3;
        aoff[j] = (long long)r * K + (f & 7) * 4;
        sa_addr[j] = sa_base + (uint32_t)((r * SLDA + (f & 7) * 4) * 4);
        int rb = f >> 5;
        boff[j] = (long long)rb * N + bn + (f & 31) * 4;
        sb_addr[j] = sb_base + (uint32_t)((rb * SLDB + (f & 31) * 4) * 4);
    }

    float acc[2][8][4];
#pragma unroll
    for (int mi = 0; mi < 2; mi++)
#pragma unroll
        for (int ni = 0; ni < 8; ni++)
#pragma unroll
            for (int c = 0; c < 4; c++) acc[mi][ni][c] = 0.f;

    auto load_stage = [&](int st, int k0) {
#pragma unroll
        for (int j = 0; j < 4; j++)
            cp_async16(sa_addr[j] + (uint32_t)(st * A_STAGE * 4), A + aoff[j] + k0);
#pragma unroll
        for (int j = 0; j < 4; j++)
            cp_async16(sb_addr[j] + (uint32_t)(st * B_STAGE * 4), B + boff[j] + (long long)k0 * N);
        cp_commit();
    };

    load_stage(0, 0);
    const int KT = K / BK;
    for (int kt = 0; kt < KT; kt++) {
        if (kt + 1 < KT) { load_stage((kt + 1) & 1, (kt + 1) * BK); cp_wait1(); }
        else             { cp_wait0(); }
        __syncthreads();
        const float* as = As0 + (kt & 1) * A_STAGE;
        const float* bs = Bs0 + (kt & 1) * B_STAGE;
#pragma unroll
        for (int kk = 0; kk < 4; kk++) {
            uint32_t af[2][4];
#pragma unroll
            for (int mi = 0; mi < 2; mi++) {
                const float* ap = as + (wm + mi * 16 + g4) * SLDA + kk * 8 + t4;
                af[mi][0] = f2tf32(ap[0]);
                af[mi][1] = f2tf32(ap[8 * SLDA]);
                af[mi][2] = f2tf32(ap[4]);
                af[mi][3] = f2tf32(ap[8 * SLDA + 4]);
            }
            uint32_t bf[8][2];
#pragma unroll
            for (int ni = 0; ni < 8; ni++) {
                const float* bp = bs + (kk * 8 + t4) * SLDB + wn + ni * 8 + g4;
                bf[ni][0] = f2tf32(bp[0]);
                bf[ni][1] = f2tf32(bp[4 * SLDB]);
            }
#pragma unroll
            for (int mi = 0; mi < 2; mi++)
#pragma unroll
                for (int ni = 0; ni < 8; ni++)
                    mma8(acc[mi][ni], af[mi], bf[ni]);
        }
        __syncthreads();
    }

#pragma unroll
    for (int mi = 0; mi < 2; mi++) {
        int r0 = wm + mi * 16 + g4;
#pragma unroll
        for (int ni = 0; ni < 8; ni++) {
            int c0 = bn + wn + ni * 8 + t4 * 2;
            *(float2*)(C + (long long)r0 * N + c0)       = make_float2(acc[mi][ni][0], acc[mi][ni][1]);
            *(float2*)(C + (long long)(r0 + 8) * N + c0) = make_float2(acc[mi][ni][2], acc[mi][ni][3]);
        }
    }
}

// Generic flat GEMM (small q / out projections)
__global__ __launch_bounds__(256) void gemm_tf32(
    const float* __restrict__ A, const float* __restrict__ B, float* __restrict__ C,
    int N, int K)
{
    gemm_body(A + (long long)(blockIdx.y * BM) * K,
              B,
              C + (long long)(blockIdx.y * BM) * N,
              N, K, blockIdx.x * BN);
}

// kv GEMM over compacted rows: per-batch tile grid with early exit.
#define KV_TILES (PADK / BM)   // 33
__global__ __launch_bounds__(256) void gemm_kv(
    const float* __restrict__ ln, const float* __restrict__ Wkv, float* __restrict__ kv,
    const int* __restrict__ cnt)
{
    const int b    = blockIdx.y / KV_TILES;
    const int tile = blockIdx.y - b * KV_TILES;
    const int bm   = tile * BM;
    if (bm >= cnt[b]) return;                      // whole CTA exits uniformly
    gemm_body(ln + ((size_t)b * PADK + bm) * DMODEL,
              Wkv,
              kv + ((size_t)b * PADK + bm) * (2 * DMODEL),
              2 * DMODEL, DMODEL, blockIdx.x * BN);
}

// ---------------- flash attention over compacted keys, one CTA per (b, h) ----------------
#define ATTN_SMEM ((3 * 64 * 68 + 64 * 65 + 64) * 4)

__global__ __launch_bounds__(256) void attn_kernel(
    const float* __restrict__ qb, const float* __restrict__ kv,
    const int* __restrict__ cnt, float* __restrict__ att)
{
    extern __shared__ float sh[];
    float* Qs = sh;                 // [64][68]
    float* Ks = Qs + 64 * 68;       // [64][68]
    float* Vs = Ks + 64 * 68;       // [64][68]
    float* Ps = Vs + 64 * 68;       // [64][65]
    float* Mk = Ps + 64 * 65;       // [64]

    const int tid = threadIdx.x;
    const int bh = blockIdx.x;
    const int b = bh >> 4, h = bh & (HEADS - 1);
    const int q = tid >> 2, sub = tid & 3;
    const int nk = cnt[b];
    const int nch = (nk + 63) >> 6;

#pragma unroll
    for (int j = 0; j < 4; j++) {
        int f = tid + j * 256;
        int r = f >> 4, c4 = f & 15;
        float4 v = *(const float4*)(qb + ((size_t)(b * NLAT + r)) * DMODEL + h * DH + c4 * 4);
        v.x *= 0.125f; v.y *= 0.125f; v.z *= 0.125f; v.w *= 0.125f;
        *(float4*)(Qs + r * 68 + c4 * 4) = v;
    }

    float4 Oa[4];
#pragma unroll
    for (int i = 0; i < 4; i++) Oa[i] = make_float4(0.f, 0.f, 0.f, 0.f);
    float mrun = -1e30f, lsum = 0.f;

    const float* kbase = kv + ((size_t)b * PADK) * 2048 + h * DH;

    for (int ch = 0; ch < nch; ch++) {
        const int j0 = ch * 64;
        __syncthreads();
#pragma unroll
        for (int j = 0; j < 4; j++) {
            int f = tid + j * 256;
            int r = f >> 4, c4 = f & 15;
            const float* rp = kbase + (size_t)(j0 + r) * 2048 + c4 * 4;
            *(float4*)(Ks + r * 68 + c4 * 4) = *(const float4*)rp;
            *(float4*)(Vs + r * 68 + c4 * 4) = *(const float4*)(rp + DMODEL);
        }
        if (tid < 64)
            Mk[tid] = (j0 + tid < nk) ? 1.f : 0.f;   // only tail chunk partially valid
        __syncthreads();

        float sreg[16];
#pragma unroll
        for (int jj = 0; jj < 16; jj++) sreg[jj] = 0.f;
#pragma unroll
        for (int d4 = 0; d4 < 16; d4++) {
            float4 qv = *(const float4*)(Qs + q * 68 + d4 * 4);
#pragma unroll
            for (int jj = 0; jj < 16; jj++) {
                float4 kvv = *(const float4*)(Ks + (4 * jj + sub) * 68 + d4 * 4);
                sreg[jj] += qv.x * kvv.x + qv.y * kvv.y + qv.z * kvv.z + qv.w * kvv.w;
            }
        }
#pragma unroll
        for (int jj = 0; jj < 16; jj++)
            if (!(Mk[4 * jj + sub] > 0.f)) sreg[jj] = -1e30f;

        float mloc = -1e30f;
#pragma unroll
        for (int jj = 0; jj < 16; jj++) mloc = fmaxf(mloc, sreg[jj]);
        mloc = fmaxf(mloc, __shfl_xor_sync(0xffffffffu, mloc, 1));
        mloc = fmaxf(mloc, __shfl_xor_sync(0xffffffffu, mloc, 2));
        float mnew = fmaxf(mrun, mloc);
        float corr = __expf(mrun - mnew);
        float psum = 0.f;
#pragma unroll
        for (int jj = 0; jj < 16; jj++) {
            int j = 4 * jj + sub;
            float p = __expf(sreg[jj] - mnew) * Mk[j];
            psum += p;
            Ps[q * 65 + j] = p;
        }
        psum += __shfl_xor_sync(0xffffffffu, psum, 1);
        psum += __shfl_xor_sync(0xffffffffu, psum, 2);
        lsum = lsum * corr + psum;
#pragma unroll
        for (int i = 0; i < 4; i++) { Oa[i].x *= corr; Oa[i].y *= corr; Oa[i].z *= corr; Oa[i].w *= corr; }
        mrun = mnew;
        __syncthreads();

#pragma unroll 4
        for (int j = 0; j < 64; j++) {
            float p = Ps[q * 65 + j];
#pragma unroll
            for (int d4 = 0; d4 < 4; d4++) {
                float4 v = *(const float4*)(Vs + j * 68 + d4 * 16 + sub * 4);
                Oa[d4].x += p * v.x; Oa[d4].y += p * v.y;
                Oa[d4].z += p * v.z; Oa[d4].w += p * v.w;
            }
        }
    }

    float rl = __fdividef(1.f, lsum);
    float* orow = att + ((size_t)(b * NLAT + q)) * DMODEL + h * DH;
#pragma unroll
    for (int d4 = 0; d4 < 4; d4++) {
        float4 v = Oa[d4];
        v.x *= rl; v.y *= rl; v.z *= rl; v.w *= rl;
        *(float4*)(orow + d4 * 16 + sub * 4) = v;
    }
}

// ---------------- launch ----------------
extern "C" void kernel_launch(void* const* d_in, const int* in_sizes, int n_in,
                              void* d_out, int out_size)
{
    const float* x    = (const float*)d_in[0];
    const float* lat  = (const float*)d_in[1];
    const int*   mask = (const int*)d_in[2];
    const float* g1   = (const float*)d_in[3];
    const float* b1   = (const float*)d_in[4];
    const float* g2   = (const float*)d_in[5];
    const float* b2   = (const float*)d_in[6];
    const float* Wq   = (const float*)d_in[7];
    const float* Wkv  = (const float*)d_in[8];
    const float* Wout = (const float*)d_in[9];
    float* out = (float*)d_out;

    float *lnp, *kvp, *lnlatp, *qp, *attp;
    int *idxp, *cntp;
    cudaGetSymbolAddress((void**)&lnp,    g_ln);
    cudaGetSymbolAddress((void**)&kvp,    g_kv);
    cudaGetSymbolAddress((void**)&lnlatp, g_lnlat);
    cudaGetSymbolAddress((void**)&qp,     g_q);
    cudaGetSymbolAddress((void**)&attp,   g_att);
    cudaGetSymbolAddress((void**)&idxp,   g_idx);
    cudaGetSymbolAddress((void**)&cntp,   g_cnt);

    cudaFuncSetAttribute(gemm_kv,     cudaFuncAttributeMaxDynamicSharedMemorySize, GEMM_SMEM);
    cudaFuncSetAttribute(gemm_tf32,   cudaFuncAttributeMaxDynamicSharedMemorySize, GEMM_SMEM);
    cudaFuncSetAttribute(attn_kernel, cudaFuncAttributeMaxDynamicSharedMemorySize, ATTN_SMEM);

    // 1. compact unmasked token indices (+ latents) per batch
    compact_kernel<<<BATCH, 1024>>>(mask, idxp, cntp);

    // 2. LN(latents) dense (for q)
    ln_dense<<<BATCH * NLAT, 256>>>(lat, g2, b2, lnlatp);

    // 3. LN in compacted key order (tokens + latents + pad)
    ln_gather<<<dim3(PADK, BATCH), 256>>>(x, lat, idxp, cntp, g1, b1, g2, b2, lnp);

    // 4. kv = ln_compact @ Wkv  (only live tiles compute)
    gemm_kv<<<dim3(2 * DMODEL / BN, BATCH * KV_TILES), 256, GEMM_SMEM>>>(
        lnp, Wkv, kvp, cntp);

    // 5. q = LN(latents) @ Wq
    gemm_tf32<<<dim3(DMODEL / BN, (BATCH * NLAT) / BM), 256, GEMM_SMEM>>>(
        lnlatp, Wq, qp, DMODEL, DMODEL);

    // 6. attention over compacted keys
    attn_kernel<<<BATCH * HEADS, 256, ATTN_SMEM>>>(qp, kvp, cntp, attp);

    // 7. out = att @ Wout
    gemm_tf32<<<dim3(DMODEL / BN, (BATCH * NLAT) / BM), 256, GEMM_SMEM>>>(
        attp, Wout, out, DMODEL, DMODEL);
}

// round 9
// speedup vs baseline: 1.8348x; 1.0233x over previous
#include <cuda_runtime.h>
#include <cstdint>

#define BATCH 8
#define NTOK 4096
#define NLAT 64
#define PADK 4224              // padded compacted-key capacity per batch (33 * 128)
#define DMODEL 1024
#define HEADS 16
#define DH 64

// ---------------- scratch (static device memory; no allocations) ----------------
__device__ float g_ln   [(size_t)BATCH * PADK * DMODEL];       // LN rows, compacted order, tf32-rounded
__device__ float g_kv   [(size_t)BATCH * PADK * 2 * DMODEL];   // [b, slot, 2048] : k | v (fp32)
__device__ float g_lnlat[(size_t)BATCH * NLAT * DMODEL];       // dense LN(latents), tf32-rounded
__device__ float g_q    [(size_t)BATCH * NLAT * DMODEL];       // fp32
__device__ float g_att  [(size_t)BATCH * NLAT * DMODEL];       // tf32-rounded
__device__ int   g_idx  [(size_t)BATCH * PADK];
__device__ int   g_cnt  [BATCH];
// tf32-rounded weights: Wkv (1024x2048) | Wq (1024x1024) | Wout (1024x1024)
__device__ float g_wr   [(size_t)4 * DMODEL * DMODEL];
#define WR_KV   0
#define WR_Q    ((size_t)2 * DMODEL * DMODEL)
#define WR_OUT  ((size_t)3 * DMODEL * DMODEL)

// ---------------- helpers ----------------
__device__ __forceinline__ uint32_t smem_u32(const void* p) {
    uint32_t a;
    asm("{ .reg .u64 t; cvta.to.shared.u64 t, %1; cvt.u32.u64 %0, t; }" : "=r"(a) : "l"(p));
    return a;
}
__device__ __forceinline__ void cp_async16(uint32_t s, const void* g) {
    asm volatile("cp.async.cg.shared.global [%0], [%1], 16;\n" :: "r"(s), "l"(g));
}
__device__ __forceinline__ void cp_commit() { asm volatile("cp.async.commit_group;\n" ::); }
__device__ __forceinline__ void cp_wait0()  { asm volatile("cp.async.wait_group 0;\n" ::); }
__device__ __forceinline__ void cp_wait1()  { asm volatile("cp.async.wait_group 1;\n" ::); }

__device__ __forceinline__ uint32_t f2tf32(float f) {
    uint32_t r; asm volatile("cvt.rna.tf32.f32 %0, %1;\n" : "=r"(r) : "f"(f)); return r;
}
__device__ __forceinline__ void mma8(float* d, const uint32_t* a, const uint32_t* b) {
    asm volatile(
        "mma.sync.aligned.m16n8k8.row.col.f32.tf32.tf32.f32 "
        "{%0,%1,%2,%3}, {%4,%5,%6,%7}, {%8,%9}, {%0,%1,%2,%3};\n"
        : "+f"(d[0]), "+f"(d[1]), "+f"(d[2]), "+f"(d[3])
        : "r"(a[0]), "r"(a[1]), "r"(a[2]), "r"(a[3]), "r"(b[0]), "r"(b[1]));
}

// ---------------- one-shot weight rounding (Wkv | Wq | Wout -> g_wr) ----------------
__global__ __launch_bounds__(256) void round_weights(
    const float* __restrict__ wkv, const float* __restrict__ wq,
    const float* __restrict__ wout, float* __restrict__ dst)
{
    const size_t i = ((size_t)blockIdx.x * 256 + threadIdx.x) * 4;   // over 4M elements
    const size_t n_kv = (size_t)2 * DMODEL * DMODEL;
    const size_t n_1  = (size_t)DMODEL * DMODEL;
    const float* src;
    size_t off;
    if (i < n_kv)            { src = wkv;  off = i; }
    else if (i < n_kv + n_1) { src = wq;   off = i - n_kv; }
    else                     { src = wout; off = i - n_kv - n_1; }
    float4 v = *(const float4*)(src + off);
    v.x = __uint_as_float(f2tf32(v.x));
    v.y = __uint_as_float(f2tf32(v.y));
    v.z = __uint_as_float(f2tf32(v.z));
    v.w = __uint_as_float(f2tf32(v.w));
    *(float4*)(dst + i) = v;
}

// ---------------- mask compaction: deterministic block prefix-sum ----------------
__global__ __launch_bounds__(1024) void compact_kernel(
    const int* __restrict__ mask, int* __restrict__ idx, int* __restrict__ cnt)
{
    __shared__ int wsum[32];
    __shared__ int stotal;
    const int b = blockIdx.x, t = threadIdx.x;
    const int* mb = mask + (size_t)b * NTOK;
    const int base4 = t * 4;
    int m0 = mb[base4 + 0] != 0, m1 = mb[base4 + 1] != 0;
    int m2 = mb[base4 + 2] != 0, m3 = mb[base4 + 3] != 0;
    const int s = m0 + m1 + m2 + m3;
    const int lane = t & 31, w = t >> 5;
    int inc = s;
#pragma unroll
    for (int o = 1; o < 32; o <<= 1) {
        int v = __shfl_up_sync(0xffffffffu, inc, o);
        if (lane >= o) inc += v;
    }
    if (lane == 31) wsum[w] = inc;
    __syncthreads();
    if (w == 0) {
        int v = wsum[lane];
#pragma unroll
        for (int o = 1; o < 32; o <<= 1) {
            int u = __shfl_up_sync(0xffffffffu, v, o);
            if (lane >= o) v += u;
        }
        wsum[lane] = v;
    }
    __syncthreads();
    const int basep = inc - s + (w ? wsum[w - 1] : 0);
    int* ib = idx + (size_t)b * PADK;
    int p = basep;
    if (m0) ib[p++] = base4 + 0;
    if (m1) ib[p++] = base4 + 1;
    if (m2) ib[p++] = base4 + 2;
    if (m3) ib[p++] = base4 + 3;
    if (t == 1023) stotal = basep + s;
    __syncthreads();
    const int total = stotal;
    if (t < NLAT) ib[total + t] = NTOK + t;
    for (int j = total + NLAT + t; j < PADK; j += 1024) ib[j] = NTOK;
    if (t == 0) cnt[b] = total + NLAT;
}

// ---------------- shared LN row body (256 threads, 4 floats/thread), tf32-rounded out ----------------
__device__ __forceinline__ void ln_row(const float* __restrict__ xr,
                                       const float* __restrict__ gamma,
                                       const float* __restrict__ beta,
                                       float* __restrict__ outr)
{
    const int t = threadIdx.x;
    float4 v = ((const float4*)xr)[t];
    float s  = v.x + v.y + v.z + v.w;
    float ss = v.x*v.x + v.y*v.y + v.z*v.z + v.w*v.w;
#pragma unroll
    for (int o = 16; o; o >>= 1) {
        s  += __shfl_xor_sync(0xffffffffu, s, o);
        ss += __shfl_xor_sync(0xffffffffu, ss, o);
    }
    __shared__ float rs[8], rss[8];
    if ((t & 31) == 0) { rs[t >> 5] = s; rss[t >> 5] = ss; }
    __syncthreads();
    float sum = 0.f, sq = 0.f;
#pragma unroll
    for (int i = 0; i < 8; i++) { sum += rs[i]; sq += rss[i]; }
    const float mu  = sum * (1.f / DMODEL);
    const float inv = rsqrtf(sq * (1.f / DMODEL) - mu * mu + 1e-5f);
    float4 g  = ((const float4*)gamma)[t];
    float4 bb = ((const float4*)beta)[t];
    float4 o;
    o.x = __uint_as_float(f2tf32((v.x - mu) * inv * g.x + bb.x));
    o.y = __uint_as_float(f2tf32((v.y - mu) * inv * g.y + bb.y));
    o.z = __uint_as_float(f2tf32((v.z - mu) * inv * g.z + bb.z));
    o.w = __uint_as_float(f2tf32((v.w - mu) * inv * g.w + bb.w));
    ((float4*)outr)[t] = o;
}

__global__ __launch_bounds__(256) void ln_dense(
    const float* __restrict__ in, const float* __restrict__ gamma,
    const float* __restrict__ beta, float* __restrict__ out)
{
    const size_t row = blockIdx.x;
    ln_row(in + row * DMODEL, gamma, beta, out + row * DMODEL);
}

__global__ __launch_bounds__(256) void ln_gather(
    const float* __restrict__ x, const float* __restrict__ lat,
    const int* __restrict__ idx, const int* __restrict__ cnt,
    const float* __restrict__ g1, const float* __restrict__ b1,
    const float* __restrict__ g2, const float* __restrict__ b2,
    float* __restrict__ out)
{
    const int b = blockIdx.y;
    const int slot = blockIdx.x;
    const int nk = cnt[b];
    if (slot >= ((nk + 127) & ~127)) return;
    const int g = idx[(size_t)b * PADK + slot];
    const float* src;
    const float *gam, *bet;
    if (g < NTOK) { src = x   + ((size_t)b * NTOK + g) * DMODEL;          gam = g1; bet = b1; }
    else          { src = lat + ((size_t)b * NLAT + (g - NTOK)) * DMODEL; gam = g2; bet = b2; }
    ln_row(src, gam, bet, out + ((size_t)b * PADK + slot) * DMODEL);
}

// ---------------- tf32 mma.sync GEMM, pre-rounded operands (no CVT in loop) ----------------
#define BM 128
#define BN 128
#define BK 32
#define SLDA 36
#define SLDB 136
#define A_STAGE (BM * SLDA)
#define B_STAGE (BK * SLDB)
#define GEMM_SMEM ((2 * A_STAGE + 2 * B_STAGE) * 4)

__device__ __forceinline__ void gemm_body(
    const float* __restrict__ A, const float* __restrict__ B, float* __restrict__ C,
    int N, int K, int bn)
{
    extern __shared__ float sm[];
    float* As0 = sm;
    float* Bs0 = sm + 2 * A_STAGE;
    const int tid  = threadIdx.x;
    const int warp = tid >> 5, lane = tid & 31;
    const int wm = (warp >> 1) * 32, wn = (warp & 1) * 64;
    const int g4 = lane >> 2, t4 = lane & 3;

    uint32_t sa_base = smem_u32(As0);
    uint32_t sb_base = smem_u32(Bs0);

    long long aoff[4], boff[4];
    uint32_t  sa_addr[4], sb_addr[4];
#pragma unroll
    for (int j = 0; j < 4; j++) {
        int f = tid + j * 256;
        int r = f >> 3;
        aoff[j] = (long long)r * K + (f & 7) * 4;
        sa_addr[j] = sa_base + (uint32_t)((r * SLDA + (f & 7) * 4) * 4);
        int rb = f >> 5;
        boff[j] = (long long)rb * N + bn + (f & 31) * 4;
        sb_addr[j] = sb_base + (uint32_t)((rb * SLDB + (f & 31) * 4) * 4);
    }

    float acc[2][8][4];
#pragma unroll
    for (int mi = 0; mi < 2; mi++)
#pragma unroll
        for (int ni = 0; ni < 8; ni++)
#pragma unroll
            for (int c = 0; c < 4; c++) acc[mi][ni][c] = 0.f;

    auto load_stage = [&](int st, int k0) {
#pragma unroll
        for (int j = 0; j < 4; j++)
            cp_async16(sa_addr[j] + (uint32_t)(st * A_STAGE * 4), A + aoff[j] + k0);
#pragma unroll
        for (int j = 0; j < 4; j++)
            cp_async16(sb_addr[j] + (uint32_t)(st * B_STAGE * 4), B + boff[j] + (long long)k0 * N);
        cp_commit();
    };

    load_stage(0, 0);
    const int KT = K / BK;
    for (int kt = 0; kt < KT; kt++) {
        if (kt + 1 < KT) { load_stage((kt + 1) & 1, (kt + 1) * BK); cp_wait1(); }
        else             { cp_wait0(); }
        __syncthreads();
        const uint32_t* as = (const uint32_t*)(As0 + (kt & 1) * A_STAGE);
        const uint32_t* bs = (const uint32_t*)(Bs0 + (kt & 1) * B_STAGE);
#pragma unroll
        for (int kk = 0; kk < 4; kk++) {
            uint32_t af[2][4];
#pragma unroll
            for (int mi = 0; mi < 2; mi++) {
                const uint32_t* ap = as + (wm + mi * 16 + g4) * SLDA + kk * 8 + t4;
                af[mi][0] = ap[0];
                af[mi][1] = ap[8 * SLDA];
                af[mi][2] = ap[4];
                af[mi][3] = ap[8 * SLDA + 4];
            }
            uint32_t bf[8][2];
#pragma unroll
            for (int ni = 0; ni < 8; ni++) {
                const uint32_t* bp = bs + (kk * 8 + t4) * SLDB + wn + ni * 8 + g4;
                bf[ni][0] = bp[0];
                bf[ni][1] = bp[4 * SLDB];
            }
#pragma unroll
            for (int mi = 0; mi < 2; mi++)
#pragma unroll
                for (int ni = 0; ni < 8; ni++)
                    mma8(acc[mi][ni], af[mi], bf[ni]);
        }
        __syncthreads();
    }

#pragma unroll
    for (int mi = 0; mi < 2; mi++) {
        int r0 = wm + mi * 16 + g4;
#pragma unroll
        for (int ni = 0; ni < 8; ni++) {
            int c0 = bn + wn + ni * 8 + t4 * 2;
            *(float2*)(C + (long long)r0 * N + c0)       = make_float2(acc[mi][ni][0], acc[mi][ni][1]);
            *(float2*)(C + (long long)(r0 + 8) * N + c0) = make_float2(acc[mi][ni][2], acc[mi][ni][3]);
        }
    }
}

__global__ __launch_bounds__(256) void gemm_tf32(
    const float* __restrict__ A, const float* __restrict__ B, float* __restrict__ C,
    int N, int K)
{
    gemm_body(A + (long long)(blockIdx.y * BM) * K,
              B,
              C + (long long)(blockIdx.y * BM) * N,
              N, K, blockIdx.x * BN);
}

#define KV_TILES (PADK / BM)   // 33
__global__ __launch_bounds__(256) void gemm_kv(
    const float* __restrict__ ln, const float* __restrict__ Wkv, float* __restrict__ kv,
    const int* __restrict__ cnt)
{
    const int b    = blockIdx.y / KV_TILES;
    const int tile = blockIdx.y - b * KV_TILES;
    const int bm   = tile * BM;
    if (bm >= cnt[b]) return;
    gemm_body(ln + ((size_t)b * PADK + bm) * DMODEL,
              Wkv,
              kv + ((size_t)b * PADK + bm) * (2 * DMODEL),
              2 * DMODEL, DMODEL, blockIdx.x * BN);
}

// ---------------- flash attention over compacted keys, one CTA per (b, h) ----------------
#define ATTN_SMEM ((3 * 64 * 68 + 64 * 65 + 64) * 4)

__global__ __launch_bounds__(256) void attn_kernel(
    const float* __restrict__ qb, const float* __restrict__ kv,
    const int* __restrict__ cnt, float* __restrict__ att)
{
    extern __shared__ float sh[];
    float* Qs = sh;
    float* Ks = Qs + 64 * 68;
    float* Vs = Ks + 64 * 68;
    float* Ps = Vs + 64 * 68;
    float* Mk = Ps + 64 * 65;

    const int tid = threadIdx.x;
    const int bh = blockIdx.x;
    const int b = bh >> 4, h = bh & (HEADS - 1);
    const int q = tid >> 2, sub = tid & 3;
    const int nk = cnt[b];
    const int nch = (nk + 63) >> 6;

#pragma unroll
    for (int j = 0; j < 4; j++) {
        int f = tid + j * 256;
        int r = f >> 4, c4 = f & 15;
        float4 v = *(const float4*)(qb + ((size_t)(b * NLAT + r)) * DMODEL + h * DH + c4 * 4);
        v.x *= 0.125f; v.y *= 0.125f; v.z *= 0.125f; v.w *= 0.125f;
        *(float4*)(Qs + r * 68 + c4 * 4) = v;
    }

    float4 Oa[4];
#pragma unroll
    for (int i = 0; i < 4; i++) Oa[i] = make_float4(0.f, 0.f, 0.f, 0.f);
    float mrun = -1e30f, lsum = 0.f;

    const float* kbase = kv + ((size_t)b * PADK) * 2048 + h * DH;

    for (int ch = 0; ch < nch; ch++) {
        const int j0 = ch * 64;
        __syncthreads();
#pragma unroll
        for (int j = 0; j < 4; j++) {
            int f = tid + j * 256;
            int r = f >> 4, c4 = f & 15;
            const float* rp = kbase + (size_t)(j0 + r) * 2048 + c4 * 4;
            *(float4*)(Ks + r * 68 + c4 * 4) = *(const float4*)rp;
            *(float4*)(Vs + r * 68 + c4 * 4) = *(const float4*)(rp + DMODEL);
        }
        if (tid < 64)
            Mk[tid] = (j0 + tid < nk) ? 1.f : 0.f;
        __syncthreads();

        float sreg[16];
#pragma unroll
        for (int jj = 0; jj < 16; jj++) sreg[jj] = 0.f;
#pragma unroll
        for (int d4 = 0; d4 < 16; d4++) {
            float4 qv = *(const float4*)(Qs + q * 68 + d4 * 4);
#pragma unroll
            for (int jj = 0; jj < 16; jj++) {
                float4 kvv = *(const float4*)(Ks + (4 * jj + sub) * 68 + d4 * 4);
                sreg[jj] += qv.x * kvv.x + qv.y * kvv.y + qv.z * kvv.z + qv.w * kvv.w;
            }
        }
#pragma unroll
        for (int jj = 0; jj < 16; jj++)
            if (!(Mk[4 * jj + sub] > 0.f)) sreg[jj] = -1e30f;

        float mloc = -1e30f;
#pragma unroll
        for (int jj = 0; jj < 16; jj++) mloc = fmaxf(mloc, sreg[jj]);
        mloc = fmaxf(mloc, __shfl_xor_sync(0xffffffffu, mloc, 1));
        mloc = fmaxf(mloc, __shfl_xor_sync(0xffffffffu, mloc, 2));
        float mnew = fmaxf(mrun, mloc);
        float corr = __expf(mrun - mnew);
        float psum = 0.f;
#pragma unroll
        for (int jj = 0; jj < 16; jj++) {
            int j = 4 * jj + sub;
            float p = __expf(sreg[jj] - mnew) * Mk[j];
            psum += p;
            Ps[q * 65 + j] = p;
        }
        psum += __shfl_xor_sync(0xffffffffu, psum, 1);
        psum += __shfl_xor_sync(0xffffffffu, psum, 2);
        lsum = lsum * corr + psum;
#pragma unroll
        for (int i = 0; i < 4; i++) { Oa[i].x *= corr; Oa[i].y *= corr; Oa[i].z *= corr; Oa[i].w *= corr; }
        mrun = mnew;
        __syncthreads();

#pragma unroll 4
        for (int j = 0; j < 64; j++) {
            float p = Ps[q * 65 + j];
#pragma unroll
            for (int d4 = 0; d4 < 4; d4++) {
                float4 v = *(const float4*)(Vs + j * 68 + d4 * 16 + sub * 4);
                Oa[d4].x += p * v.x; Oa[d4].y += p * v.y;
                Oa[d4].z += p * v.z; Oa[d4].w += p * v.w;
            }
        }
    }

    // write tf32-rounded (att feeds the out-projection GEMM; identical to GEMM-side cvt)
    float rl = __fdividef(1.f, lsum);
    float* orow = att + ((size_t)(b * NLAT + q)) * DMODEL + h * DH;
#pragma unroll
    for (int d4 = 0; d4 < 4; d4++) {
        float4 v = Oa[d4];
        v.x = __uint_as_float(f2tf32(v.x * rl));
        v.y = __uint_as_float(f2tf32(v.y * rl));
        v.z = __uint_as_float(f2tf32(v.z * rl));
        v.w = __uint_as_float(f2tf32(v.w * rl));
        *(float4*)(orow + d4 * 16 + sub * 4) = v;
    }
}

// ---------------- launch ----------------
extern "C" void kernel_launch(void* const* d_in, const int* in_sizes, int n_in,
                              void* d_out, int out_size)
{
    const float* x    = (const float*)d_in[0];
    const float* lat  = (const float*)d_in[1];
    const int*   mask = (const int*)d_in[2];
    const float* g1   = (const float*)d_in[3];
    const float* b1   = (const float*)d_in[4];
    const float* g2   = (const float*)d_in[5];
    const float* b2   = (const float*)d_in[6];
    const float* Wq   = (const float*)d_in[7];
    const float* Wkv  = (const float*)d_in[8];
    const float* Wout = (const float*)d_in[9];
    float* out = (float*)d_out;

    float *lnp, *kvp, *lnlatp, *qp, *attp, *wrp;
    int *idxp, *cntp;
    cudaGetSymbolAddress((void**)&lnp,    g_ln);
    cudaGetSymbolAddress((void**)&kvp,    g_kv);
    cudaGetSymbolAddress((void**)&lnlatp, g_lnlat);
    cudaGetSymbolAddress((void**)&qp,     g_q);
    cudaGetSymbolAddress((void**)&attp,   g_att);
    cudaGetSymbolAddress((void**)&wrp,    g_wr);
    cudaGetSymbolAddress((void**)&idxp,   g_idx);
    cudaGetSymbolAddress((void**)&cntp,   g_cnt);

    cudaFuncSetAttribute(gemm_kv,     cudaFuncAttributeMaxDynamicSharedMemorySize, GEMM_SMEM);
    cudaFuncSetAttribute(gemm_tf32,   cudaFuncAttributeMaxDynamicSharedMemorySize, GEMM_SMEM);
    cudaFuncSetAttribute(attn_kernel, cudaFuncAttributeMaxDynamicSharedMemorySize, ATTN_SMEM);

    // 0. round all weights to tf32 once per call (4M elements / 4 per thread)
    round_weights<<<(4 * DMODEL * DMODEL / 4) / 256, 256>>>(Wkv, Wq, Wout, wrp);

    // 1. compact unmasked token indices (+ latents) per batch
    compact_kernel<<<BATCH, 1024>>>(mask, idxp, cntp);

    // 2. LN(latents) dense (for q)
    ln_dense<<<BATCH * NLAT, 256>>>(lat, g2, b2, lnlatp);

    // 3. LN in compacted key order
    ln_gather<<<dim3(PADK, BATCH), 256>>>(x, lat, idxp, cntp, g1, b1, g2, b2, lnp);

    // 4. kv = ln_compact @ Wkv
    gemm_kv<<<dim3(2 * DMODEL / BN, BATCH * KV_TILES), 256, GEMM_SMEM>>>(
        lnp, wrp + WR_KV, kvp, cntp);

    // 5. q = LN(latents) @ Wq
    gemm_tf32<<<dim3(DMODEL / BN, (BATCH * NLAT) / BM), 256, GEMM_SMEM>>>(
        lnlatp, wrp + WR_Q, qp, DMODEL, DMODEL);

    // 6. attention over compacted keys
    attn_kernel<<<BATCH * HEADS, 256, ATTN_SMEM>>>(qp, kvp, cntp, attp);

    // 7. out = att @ Wout
    gemm_tf32<<<dim3(DMODEL / BN, (BATCH * NLAT) / BM), 256, GEMM_SMEM>>>(
        attp, wrp + WR_OUT, out, DMODEL, DMODEL);
}

// round 11
// speedup vs baseline: 1.8545x; 1.0107x over previous
#include <cuda_runtime.h>
#include <cstdint>

#define BATCH 8
#define NTOK 4096
#define NLAT 64
#define PADK 4224              // padded compacted-key capacity per batch (33 * 128)
#define DMODEL 1024
#define HEADS 16
#define DH 64

// ---------------- scratch (static device memory; no allocations) ----------------
__device__ float g_ln   [(size_t)BATCH * PADK * DMODEL];       // LN rows, compacted order, tf32-rounded
__device__ float g_kv   [(size_t)BATCH * PADK * 2 * DMODEL];   // [b, slot, 2048] : k | v (fp32)
__device__ float g_lnlat[(size_t)BATCH * NLAT * DMODEL];       // dense LN(latents), tf32-rounded
__device__ float g_q    [(size_t)BATCH * NLAT * DMODEL];       // fp32
__device__ float g_att  [(size_t)BATCH * NLAT * DMODEL];       // tf32-rounded
__device__ int   g_idx  [(size_t)BATCH * PADK];
__device__ int   g_cnt  [BATCH];
// tf32-rounded weights: Wkv (1024x2048) | Wq (1024x1024) | Wout (1024x1024)
__device__ float g_wr   [(size_t)4 * DMODEL * DMODEL];
#define WR_KV   0
#define WR_Q    ((size_t)2 * DMODEL * DMODEL)
#define WR_OUT  ((size_t)3 * DMODEL * DMODEL)

// ---------------- helpers ----------------
__device__ __forceinline__ uint32_t smem_u32(const void* p) {
    uint32_t a;
    asm("{ .reg .u64 t; cvta.to.shared.u64 t, %1; cvt.u32.u64 %0, t; }" : "=r"(a) : "l"(p));
    return a;
}
__device__ __forceinline__ void cp_async16(uint32_t s, const void* g) {
    asm volatile("cp.async.cg.shared.global [%0], [%1], 16;\n" :: "r"(s), "l"(g));
}
__device__ __forceinline__ void cp_commit() { asm volatile("cp.async.commit_group;\n" ::); }
__device__ __forceinline__ void cp_wait0()  { asm volatile("cp.async.wait_group 0;\n" ::); }
__device__ __forceinline__ void cp_wait1()  { asm volatile("cp.async.wait_group 1;\n" ::); }

__device__ __forceinline__ uint32_t f2tf32(float f) {
    uint32_t r; asm volatile("cvt.rna.tf32.f32 %0, %1;\n" : "=r"(r) : "f"(f)); return r;
}
__device__ __forceinline__ void mma8(float* d, const uint32_t* a, const uint32_t* b) {
    asm volatile(
        "mma.sync.aligned.m16n8k8.row.col.f32.tf32.tf32.f32 "
        "{%0,%1,%2,%3}, {%4,%5,%6,%7}, {%8,%9}, {%0,%1,%2,%3};\n"
        : "+f"(d[0]), "+f"(d[1]), "+f"(d[2]), "+f"(d[3])
        : "r"(a[0]), "r"(a[1]), "r"(a[2]), "r"(a[3]), "r"(b[0]), "r"(b[1]));
}

// ---------------- one-shot weight rounding (Wkv | Wq | Wout -> g_wr) ----------------
__global__ __launch_bounds__(256) void round_weights(
    const float* __restrict__ wkv, const float* __restrict__ wq,
    const float* __restrict__ wout, float* __restrict__ dst)
{
    const size_t i = ((size_t)blockIdx.x * 256 + threadIdx.x) * 4;
    const size_t n_kv = (size_t)2 * DMODEL * DMODEL;
    const size_t n_1  = (size_t)DMODEL * DMODEL;
    const float* src;
    size_t off;
    if (i < n_kv)            { src = wkv;  off = i; }
    else if (i < n_kv + n_1) { src = wq;   off = i - n_kv; }
    else                     { src = wout; off = i - n_kv - n_1; }
    float4 v = *(const float4*)(src + off);
    v.x = __uint_as_float(f2tf32(v.x));
    v.y = __uint_as_float(f2tf32(v.y));
    v.z = __uint_as_float(f2tf32(v.z));
    v.w = __uint_as_float(f2tf32(v.w));
    *(float4*)(dst + i) = v;
}

// ---------------- mask compaction: deterministic block prefix-sum ----------------
__global__ __launch_bounds__(1024) void compact_kernel(
    const int* __restrict__ mask, int* __restrict__ idx, int* __restrict__ cnt)
{
    __shared__ int wsum[32];
    __shared__ int stotal;
    const int b = blockIdx.x, t = threadIdx.x;
    const int* mb = mask + (size_t)b * NTOK;
    const int base4 = t * 4;
    int m0 = mb[base4 + 0] != 0, m1 = mb[base4 + 1] != 0;
    int m2 = mb[base4 + 2] != 0, m3 = mb[base4 + 3] != 0;
    const int s = m0 + m1 + m2 + m3;
    const int lane = t & 31, w = t >> 5;
    int inc = s;
#pragma unroll
    for (int o = 1; o < 32; o <<= 1) {
        int v = __shfl_up_sync(0xffffffffu, inc, o);
        if (lane >= o) inc += v;
    }
    if (lane == 31) wsum[w] = inc;
    __syncthreads();
    if (w == 0) {
        int v = wsum[lane];
#pragma unroll
        for (int o = 1; o < 32; o <<= 1) {
            int u = __shfl_up_sync(0xffffffffu, v, o);
            if (lane >= o) v += u;
        }
        wsum[lane] = v;
    }
    __syncthreads();
    const int basep = inc - s + (w ? wsum[w - 1] : 0);
    int* ib = idx + (size_t)b * PADK;
    int p = basep;
    if (m0) ib[p++] = base4 + 0;
    if (m1) ib[p++] = base4 + 1;
    if (m2) ib[p++] = base4 + 2;
    if (m3) ib[p++] = base4 + 3;
    if (t == 1023) stotal = basep + s;
    __syncthreads();
    const int total = stotal;
    if (t < NLAT) ib[total + t] = NTOK + t;
    for (int j = total + NLAT + t; j < PADK; j += 1024) ib[j] = NTOK;
    if (t == 0) cnt[b] = total + NLAT;
}

// ---------------- shared LN row body (tf32-rounded out) ----------------
__device__ __forceinline__ void ln_row(const float* __restrict__ xr,
                                       const float* __restrict__ gamma,
                                       const float* __restrict__ beta,
                                       float* __restrict__ outr)
{
    const int t = threadIdx.x;
    float4 v = ((const float4*)xr)[t];
    float s  = v.x + v.y + v.z + v.w;
    float ss = v.x*v.x + v.y*v.y + v.z*v.z + v.w*v.w;
#pragma unroll
    for (int o = 16; o; o >>= 1) {
        s  += __shfl_xor_sync(0xffffffffu, s, o);
        ss += __shfl_xor_sync(0xffffffffu, ss, o);
    }
    __shared__ float rs[8], rss[8];
    if ((t & 31) == 0) { rs[t >> 5] = s; rss[t >> 5] = ss; }
    __syncthreads();
    float sum = 0.f, sq = 0.f;
#pragma unroll
    for (int i = 0; i < 8; i++) { sum += rs[i]; sq += rss[i]; }
    const float mu  = sum * (1.f / DMODEL);
    const float inv = rsqrtf(sq * (1.f / DMODEL) - mu * mu + 1e-5f);
    float4 g  = ((const float4*)gamma)[t];
    float4 bb = ((const float4*)beta)[t];
    float4 o;
    o.x = __uint_as_float(f2tf32((v.x - mu) * inv * g.x + bb.x));
    o.y = __uint_as_float(f2tf32((v.y - mu) * inv * g.y + bb.y));
    o.z = __uint_as_float(f2tf32((v.z - mu) * inv * g.z + bb.z));
    o.w = __uint_as_float(f2tf32((v.w - mu) * inv * g.w + bb.w));
    ((float4*)outr)[t] = o;
}

__global__ __launch_bounds__(256) void ln_dense(
    const float* __restrict__ in, const float* __restrict__ gamma,
    const float* __restrict__ beta, float* __restrict__ out)
{
    const size_t row = blockIdx.x;
    ln_row(in + row * DMODEL, gamma, beta, out + row * DMODEL);
}

__global__ __launch_bounds__(256) void ln_gather(
    const float* __restrict__ x, const float* __restrict__ lat,
    const int* __restrict__ idx, const int* __restrict__ cnt,
    const float* __restrict__ g1, const float* __restrict__ b1,
    const float* __restrict__ g2, const float* __restrict__ b2,
    float* __restrict__ out)
{
    const int b = blockIdx.y;
    const int slot = blockIdx.x;
    const int nk = cnt[b];
    if (slot >= ((nk + 127) & ~127)) return;
    const int g = idx[(size_t)b * PADK + slot];
    const float* src;
    const float *gam, *bet;
    if (g < NTOK) { src = x   + ((size_t)b * NTOK + g) * DMODEL;          gam = g1; bet = b1; }
    else          { src = lat + ((size_t)b * NLAT + (g - NTOK)) * DMODEL; gam = g2; bet = b2; }
    ln_row(src, gam, bet, out + ((size_t)b * PADK + slot) * DMODEL);
}

// ---------------- small tf32 GEMM (128x128 tile, 32x64/warp) — q & out projections ----------------
#define BM 128
#define BN 128
#define BK 32
#define SLDA 36
#define SLDB 136
#define A_STAGE (BM * SLDA)
#define B_STAGE (BK * SLDB)
#define GEMM_SMEM ((2 * A_STAGE + 2 * B_STAGE) * 4)

__global__ __launch_bounds__(256) void gemm_tf32(
    const float* __restrict__ Ag, const float* __restrict__ B, float* __restrict__ C,
    int N, int K)
{
    const float* A = Ag + (long long)(blockIdx.y * BM) * K;
    C += (long long)(blockIdx.y * BM) * N;
    const int bn = blockIdx.x * BN;

    extern __shared__ float sm[];
    float* As0 = sm;
    float* Bs0 = sm + 2 * A_STAGE;
    const int tid  = threadIdx.x;
    const int warp = tid >> 5, lane = tid & 31;
    const int wm = (warp >> 1) * 32, wn = (warp & 1) * 64;
    const int g4 = lane >> 2, t4 = lane & 3;

    uint32_t sa_base = smem_u32(As0);
    uint32_t sb_base = smem_u32(Bs0);

    long long aoff[4], boff[4];
    uint32_t  sa_addr[4], sb_addr[4];
#pragma unroll
    for (int j = 0; j < 4; j++) {
        int f = tid + j * 256;
        int r = f >> 3;
        aoff[j] = (long long)r * K + (f & 7) * 4;
        sa_addr[j] = sa_base + (uint32_t)((r * SLDA + (f & 7) * 4) * 4);
        int rb = f >> 5;
        boff[j] = (long long)rb * N + bn + (f & 31) * 4;
        sb_addr[j] = sb_base + (uint32_t)((rb * SLDB + (f & 31) * 4) * 4);
    }

    float acc[2][8][4];
#pragma unroll
    for (int mi = 0; mi < 2; mi++)
#pragma unroll
        for (int ni = 0; ni < 8; ni++)
#pragma unroll
            for (int c = 0; c < 4; c++) acc[mi][ni][c] = 0.f;

    auto load_stage = [&](int st, int k0) {
#pragma unroll
        for (int j = 0; j < 4; j++)
            cp_async16(sa_addr[j] + (uint32_t)(st * A_STAGE * 4), A + aoff[j] + k0);
#pragma unroll
        for (int j = 0; j < 4; j++)
            cp_async16(sb_addr[j] + (uint32_t)(st * B_STAGE * 4), B + boff[j] + (long long)k0 * N);
        cp_commit();
    };

    load_stage(0, 0);
    const int KT = K / BK;
    for (int kt = 0; kt < KT; kt++) {
        if (kt + 1 < KT) { load_stage((kt + 1) & 1, (kt + 1) * BK); cp_wait1(); }
        else             { cp_wait0(); }
        __syncthreads();
        const uint32_t* as = (const uint32_t*)(As0 + (kt & 1) * A_STAGE);
        const uint32_t* bs = (const uint32_t*)(Bs0 + (kt & 1) * B_STAGE);
#pragma unroll
        for (int kk = 0; kk < 4; kk++) {
            uint32_t af[2][4];
#pragma unroll
            for (int mi = 0; mi < 2; mi++) {
                const uint32_t* ap = as + (wm + mi * 16 + g4) * SLDA + kk * 8 + t4;
                af[mi][0] = ap[0];
                af[mi][1] = ap[8 * SLDA];
                af[mi][2] = ap[4];
                af[mi][3] = ap[8 * SLDA + 4];
            }
            uint32_t bf[8][2];
#pragma unroll
            for (int ni = 0; ni < 8; ni++) {
                const uint32_t* bp = bs + (kk * 8 + t4) * SLDB + wn + ni * 8 + g4;
                bf[ni][0] = bp[0];
                bf[ni][1] = bp[4 * SLDB];
            }
#pragma unroll
            for (int mi = 0; mi < 2; mi++)
#pragma unroll
                for (int ni = 0; ni < 8; ni++)
                    mma8(acc[mi][ni], af[mi], bf[ni]);
        }
        __syncthreads();
    }

#pragma unroll
    for (int mi = 0; mi < 2; mi++) {
        int r0 = wm + mi * 16 + g4;
#pragma unroll
        for (int ni = 0; ni < 8; ni++) {
            int c0 = bn + wn + ni * 8 + t4 * 2;
            *(float2*)(C + (long long)r0 * N + c0)       = make_float2(acc[mi][ni][0], acc[mi][ni][1]);
            *(float2*)(C + (long long)(r0 + 8) * N + c0) = make_float2(acc[mi][ni][2], acc[mi][ni][3]);
        }
    }
}

// ---------------- kv GEMM: 128x256 CTA tile, 64x64 per warp (1.0 LDS/mma) ----------------
#define KBM 128
#define KBN 256
#define KSLDA 36                    // 32 + 4 pad (floats)
#define KSLDB 264                   // 256 + 8 pad (floats)
#define KA_ST (KBM * KSLDA * 4)     // 18432 B per stage
#define KB_ST (BK * KSLDB * 4)      // 33792 B per stage
#define KSTG  (KA_ST + KB_ST)       // 52224 B
#define KV_SMEM (2 * KSTG)          // 104448 B
#define KV_TILES (PADK / KBM)       // 33

__global__ __launch_bounds__(256, 1) void gemm_kv(
    const float* __restrict__ ln, const float* __restrict__ Wkv, float* __restrict__ kv,
    const int* __restrict__ cnt)
{
    const int b    = blockIdx.y / KV_TILES;
    const int tile = blockIdx.y - b * KV_TILES;
    const int bm   = tile * KBM;
    if (bm >= cnt[b]) return;

    const float* A = ln + ((size_t)b * PADK + bm) * DMODEL;
    float* C = kv + ((size_t)b * PADK + bm) * (2 * DMODEL);
    const int N = 2 * DMODEL;
    const int bn = blockIdx.x * KBN;

    extern __shared__ float sm[];
    const int tid  = threadIdx.x;
    const int warp = tid >> 5, lane = tid & 31;
    const int wm = (warp >> 2) * 64;      // 2 warps in m
    const int wn = (warp & 3) * 64;       // 4 warps in n
    const int g4 = lane >> 2, t4 = lane & 3;

    const uint32_t s_base = smem_u32(sm);

    // A staging: thread covers rows (tid>>3) + 32j, float4 col tid&7
    const int ar = tid >> 3, ac = tid & 7;
    const long long aoff0 = (long long)ar * DMODEL + ac * 4;
    const uint32_t sa0 = s_base + (uint32_t)((ar * KSLDA + ac * 4) * 4);
    // B staging: thread covers row (tid>>6) + 4j, float4 col tid&63
    const int br = tid >> 6, bc = tid & 63;
    const long long boff0 = (long long)br * N + bn + bc * 4;
    const uint32_t sb0 = s_base + KA_ST + (uint32_t)((br * KSLDB + bc * 4) * 4);

    float acc[4][8][4];
#pragma unroll
    for (int mi = 0; mi < 4; mi++)
#pragma unroll
        for (int ni = 0; ni < 8; ni++)
#pragma unroll
            for (int c = 0; c < 4; c++) acc[mi][ni][c] = 0.f;

    auto load_stage = [&](int st, int k0) {
        const float* a0 = A + aoff0 + k0;
        const uint32_t so = (uint32_t)(st * KSTG);
#pragma unroll
        for (int j = 0; j < 4; j++)
            cp_async16(sa0 + so + (uint32_t)(j * 32 * KSLDA * 4), a0 + (long long)j * 32 * DMODEL);
        const float* b0 = Wkv + boff0 + (long long)k0 * N;
#pragma unroll
        for (int j = 0; j < 8; j++)
            cp_async16(sb0 + so + (uint32_t)(j * 4 * KSLDB * 4), b0 + (long long)j * 4 * N);
        cp_commit();
    };

    load_stage(0, 0);
    const int KT = DMODEL / BK;   // 32
    for (int kt = 0; kt < KT; kt++) {
        if (kt + 1 < KT) { load_stage((kt + 1) & 1, (kt + 1) * BK); cp_wait1(); }
        else             { cp_wait0(); }
        __syncthreads();
        const uint32_t* as = (const uint32_t*)(sm + (kt & 1) * (KSTG / 4));
        const uint32_t* bs = as + KA_ST / 4;
#pragma unroll
        for (int kk = 0; kk < 4; kk++) {
            uint32_t af[4][4];
#pragma unroll
            for (int mi = 0; mi < 4; mi++) {
                const uint32_t* ap = as + (wm + mi * 16 + g4) * KSLDA + kk * 8 + t4;
                af[mi][0] = ap[0];
                af[mi][1] = ap[8 * KSLDA];
                af[mi][2] = ap[4];
                af[mi][3] = ap[8 * KSLDA + 4];
            }
            uint32_t bf[8][2];
#pragma unroll
            for (int ni = 0; ni < 8; ni++) {
                const uint32_t* bp = bs + (kk * 8 + t4) * KSLDB + wn + ni * 8 + g4;
                bf[ni][0] = bp[0];
                bf[ni][1] = bp[4 * KSLDB];
            }
#pragma unroll
            for (int mi = 0; mi < 4; mi++)
#pragma unroll
                for (int ni = 0; ni < 8; ni++)
                    mma8(acc[mi][ni], af[mi], bf[ni]);
        }
        __syncthreads();
    }

#pragma unroll
    for (int mi = 0; mi < 4; mi++) {
        int r0 = wm + mi * 16 + g4;
#pragma unroll
        for (int ni = 0; ni < 8; ni++) {
            int c0 = bn + wn + ni * 8 + t4 * 2;
            *(float2*)(C + (long long)r0 * N + c0)       = make_float2(acc[mi][ni][0], acc[mi][ni][1]);
            *(float2*)(C + (long long)(r0 + 8) * N + c0) = make_float2(acc[mi][ni][2], acc[mi][ni][3]);
        }
    }
}

// ---------------- flash attention over compacted keys, one CTA per (b, h) ----------------
#define ATTN_SMEM ((3 * 64 * 68 + 64 * 65 + 64) * 4)

__global__ __launch_bounds__(256) void attn_kernel(
    const float* __restrict__ qb, const float* __restrict__ kv,
    const int* __restrict__ cnt, float* __restrict__ att)
{
    extern __shared__ float sh[];
    float* Qs = sh;
    float* Ks = Qs + 64 * 68;
    float* Vs = Ks + 64 * 68;
    float* Ps = Vs + 64 * 68;
    float* Mk = Ps + 64 * 65;

    const int tid = threadIdx.x;
    const int bh = blockIdx.x;
    const int b = bh >> 4, h = bh & (HEADS - 1);
    const int q = tid >> 2, sub = tid & 3;
    const int nk = cnt[b];
    const int nch = (nk + 63) >> 6;

#pragma unroll
    for (int j = 0; j < 4; j++) {
        int f = tid + j * 256;
        int r = f >> 4, c4 = f & 15;
        float4 v = *(const float4*)(qb + ((size_t)(b * NLAT + r)) * DMODEL + h * DH + c4 * 4);
        v.x *= 0.125f; v.y *= 0.125f; v.z *= 0.125f; v.w *= 0.125f;
        *(float4*)(Qs + r * 68 + c4 * 4) = v;
    }

    float4 Oa[4];
#pragma unroll
    for (int i = 0; i < 4; i++) Oa[i] = make_float4(0.f, 0.f, 0.f, 0.f);
    float mrun = -1e30f, lsum = 0.f;

    const float* kbase = kv + ((size_t)b * PADK) * 2048 + h * DH;

    for (int ch = 0; ch < nch; ch++) {
        const int j0 = ch * 64;
        __syncthreads();
#pragma unroll
        for (int j = 0; j < 4; j++) {
            int f = tid + j * 256;
            int r = f >> 4, c4 = f & 15;
            const float* rp = kbase + (size_t)(j0 + r) * 2048 + c4 * 4;
            *(float4*)(Ks + r * 68 + c4 * 4) = *(const float4*)rp;
            *(float4*)(Vs + r * 68 + c4 * 4) = *(const float4*)(rp + DMODEL);
        }
        if (tid < 64)
            Mk[tid] = (j0 + tid < nk) ? 1.f : 0.f;
        __syncthreads();

        float sreg[16];
#pragma unroll
        for (int jj = 0; jj < 16; jj++) sreg[jj] = 0.f;
#pragma unroll
        for (int d4 = 0; d4 < 16; d4++) {
            float4 qv = *(const float4*)(Qs + q * 68 + d4 * 4);
#pragma unroll
            for (int jj = 0; jj < 16; jj++) {
                float4 kvv = *(const float4*)(Ks + (4 * jj + sub) * 68 + d4 * 4);
                sreg[jj] += qv.x * kvv.x + qv.y * kvv.y + qv.z * kvv.z + qv.w * kvv.w;
            }
        }
#pragma unroll
        for (int jj = 0; jj < 16; jj++)
            if (!(Mk[4 * jj + sub] > 0.f)) sreg[jj] = -1e30f;

        float mloc = -1e30f;
#pragma unroll
        for (int jj = 0; jj < 16; jj++) mloc = fmaxf(mloc, sreg[jj]);
        mloc = fmaxf(mloc, __shfl_xor_sync(0xffffffffu, mloc, 1));
        mloc = fmaxf(mloc, __shfl_xor_sync(0xffffffffu, mloc, 2));
        float mnew = fmaxf(mrun, mloc);
        float corr = __expf(mrun - mnew);
        float psum = 0.f;
#pragma unroll
        for (int jj = 0; jj < 16; jj++) {
            int j = 4 * jj + sub;
            float p = __expf(sreg[jj] - mnew) * Mk[j];
            psum += p;
            Ps[q * 65 + j] = p;
        }
        psum += __shfl_xor_sync(0xffffffffu, psum, 1);
        psum += __shfl_xor_sync(0xffffffffu, psum, 2);
        lsum = lsum * corr + psum;
#pragma unroll
        for (int i = 0; i < 4; i++) { Oa[i].x *= corr; Oa[i].y *= corr; Oa[i].z *= corr; Oa[i].w *= corr; }
        mrun = mnew;
        __syncthreads();

#pragma unroll 4
        for (int j = 0; j < 64; j++) {
            float p = Ps[q * 65 + j];
#pragma unroll
            for (int d4 = 0; d4 < 4; d4++) {
                float4 v = *(const float4*)(Vs + j * 68 + d4 * 16 + sub * 4);
                Oa[d4].x += p * v.x; Oa[d4].y += p * v.y;
                Oa[d4].z += p * v.z; Oa[d4].w += p * v.w;
            }
        }
    }

    float rl = __fdividef(1.f, lsum);
    float* orow = att + ((size_t)(b * NLAT + q)) * DMODEL + h * DH;
#pragma unroll
    for (int d4 = 0; d4 < 4; d4++) {
        float4 v = Oa[d4];
        v.x = __uint_as_float(f2tf32(v.x * rl));
        v.y = __uint_as_float(f2tf32(v.y * rl));
        v.z = __uint_as_float(f2tf32(v.z * rl));
        v.w = __uint_as_float(f2tf32(v.w * rl));
        *(float4*)(orow + d4 * 16 + sub * 4) = v;
    }
}

// ---------------- launch ----------------
extern "C" void kernel_launch(void* const* d_in, const int* in_sizes, int n_in,
                              void* d_out, int out_size)
{
    const float* x    = (const float*)d_in[0];
    const float* lat  = (const float*)d_in[1];
    const int*   mask = (const int*)d_in[2];
    const float* g1   = (const float*)d_in[3];
    const float* b1   = (const float*)d_in[4];
    const float* g2   = (const float*)d_in[5];
    const float* b2   = (const float*)d_in[6];
    const float* Wq   = (const float*)d_in[7];
    const float* Wkv  = (const float*)d_in[8];
    const float* Wout = (const float*)d_in[9];
    float* out = (float*)d_out;

    float *lnp, *kvp, *lnlatp, *qp, *attp, *wrp;
    int *idxp, *cntp;
    cudaGetSymbolAddress((void**)&lnp,    g_ln);
    cudaGetSymbolAddress((void**)&kvp,    g_kv);
    cudaGetSymbolAddress((void**)&lnlatp, g_lnlat);
    cudaGetSymbolAddress((void**)&qp,     g_q);
    cudaGetSymbolAddress((void**)&attp,   g_att);
    cudaGetSymbolAddress((void**)&wrp,    g_wr);
    cudaGetSymbolAddress((void**)&idxp,   g_idx);
    cudaGetSymbolAddress((void**)&cntp,   g_cnt);

    cudaFuncSetAttribute(gemm_kv,     cudaFuncAttributeMaxDynamicSharedMemorySize, KV_SMEM);
    cudaFuncSetAttribute(gemm_tf32,   cudaFuncAttributeMaxDynamicSharedMemorySize, GEMM_SMEM);
    cudaFuncSetAttribute(attn_kernel, cudaFuncAttributeMaxDynamicSharedMemorySize, ATTN_SMEM);

    // 0. round all weights to tf32 once per call
    round_weights<<<(4 * DMODEL * DMODEL / 4) / 256, 256>>>(Wkv, Wq, Wout, wrp);

    // 1. compact unmasked token indices (+ latents) per batch
    compact_kernel<<<BATCH, 1024>>>(mask, idxp, cntp);

    // 2. LN(latents) dense (for q)
    ln_dense<<<BATCH * NLAT, 256>>>(lat, g2, b2, lnlatp);

    // 3. LN in compacted key order
    ln_gather<<<dim3(PADK, BATCH), 256>>>(x, lat, idxp, cntp, g1, b1, g2, b2, lnp);

    // 4. kv = ln_compact @ Wkv   (128x256 tiles, 64x64/warp)
    gemm_kv<<<dim3(2 * DMODEL / KBN, BATCH * KV_TILES), 256, KV_SMEM>>>(
        lnp, wrp + WR_KV, kvp, cntp);

    // 5. q = LN(latents) @ Wq
    gemm_tf32<<<dim3(DMODEL / BN, (BATCH * NLAT) / BM), 256, GEMM_SMEM>>>(
        lnlatp, wrp + WR_Q, qp, DMODEL, DMODEL);

    // 6. attention over compacted keys
    attn_kernel<<<BATCH * HEADS, 256, ATTN_SMEM>>>(qp, kvp, cntp, attp);

    // 7. out = att @ Wout
    gemm_tf32<<<dim3(DMODEL / BN, (BATCH * NLAT) / BM), 256, GEMM_SMEM>>>(
        attp, wrp + WR_OUT, out, DMODEL, DMODEL);
}

// round 12
// speedup vs baseline: 2.2554x; 1.2162x over previous
#include <cuda_runtime.h>
#include <cuda_fp16.h>
#include <cstdint>

#define BATCH 8
#define NTOK 4096
#define NLAT 64
#define PADK 4224              // padded compacted-key capacity per batch (33 * 128)
#define DMODEL 1024
#define HEADS 16
#define DH 64

// ---------------- scratch (static device memory; no allocations) ----------------
__device__ __half g_lnh   [(size_t)BATCH * PADK * DMODEL];     // LN rows, compacted order, fp16
__device__ float  g_kv    [(size_t)BATCH * PADK * 2 * DMODEL]; // [b, slot, 2048] : k | v (fp32)
__device__ __half g_lnlath[(size_t)BATCH * NLAT * DMODEL];     // dense LN(latents), fp16
__device__ float  g_q     [(size_t)BATCH * NLAT * DMODEL];     // fp32
__device__ __half g_atth  [(size_t)BATCH * NLAT * DMODEL];     // attention out, fp16
__device__ int    g_idx   [(size_t)BATCH * PADK];
__device__ int    g_cnt   [BATCH];
// fp16 transposed weights ([n][k]-major): WkvT (2048x1024) | WqT (1024x1024) | WoutT (1024x1024)
__device__ __half g_wh    [(size_t)4 * DMODEL * DMODEL];
#define WH_KV   0
#define WH_Q    ((size_t)2 * DMODEL * DMODEL)
#define WH_OUT  ((size_t)3 * DMODEL * DMODEL)

// ---------------- helpers ----------------
__device__ __forceinline__ uint32_t smem_u32(const void* p) {
    uint32_t a;
    asm("{ .reg .u64 t; cvta.to.shared.u64 t, %1; cvt.u32.u64 %0, t; }" : "=r"(a) : "l"(p));
    return a;
}
__device__ __forceinline__ void cp_async16(uint32_t s, const void* g) {
    asm volatile("cp.async.cg.shared.global [%0], [%1], 16;\n" :: "r"(s), "l"(g));
}
__device__ __forceinline__ void cp_commit() { asm volatile("cp.async.commit_group;\n" ::); }
__device__ __forceinline__ void cp_wait0()  { asm volatile("cp.async.wait_group 0;\n" ::); }
__device__ __forceinline__ void cp_wait1()  { asm volatile("cp.async.wait_group 1;\n" ::); }

// fp16 mma: D(16x8,f32) += A(16x16,f16) * B(16x8,f16)
__device__ __forceinline__ void mma16(float* d, const uint32_t* a, const uint32_t* b) {
    asm volatile(
        "mma.sync.aligned.m16n8k16.row.col.f32.f16.f16.f32 "
        "{%0,%1,%2,%3}, {%4,%5,%6,%7}, {%8,%9}, {%0,%1,%2,%3};\n"
        : "+f"(d[0]), "+f"(d[1]), "+f"(d[2]), "+f"(d[3])
        : "r"(a[0]), "r"(a[1]), "r"(a[2]), "r"(a[3]), "r"(b[0]), "r"(b[1]));
}

// ---------------- one-shot weight transpose+convert: [K][N] f32 -> [N][K] f16 ----------------
__global__ __launch_bounds__(256) void transpose_h(
    const float* __restrict__ in, __half* __restrict__ out, int K, int N)
{
    __shared__ float t[32][33];
    const int tx = threadIdx.x, ty = threadIdx.y;
    const int x  = blockIdx.x * 32 + tx;      // n
    const int y0 = blockIdx.y * 32;           // k
#pragma unroll
    for (int i = ty; i < 32; i += 8)
        t[i][tx] = in[(size_t)(y0 + i) * N + x];
    __syncthreads();
    const int ox  = blockIdx.y * 32 + tx;     // k
    const int oy0 = blockIdx.x * 32;          // n
#pragma unroll
    for (int i = ty; i < 32; i += 8)
        out[(size_t)(oy0 + i) * K + ox] = __float2half_rn(t[tx][i]);
}

// ---------------- mask compaction: deterministic block prefix-sum ----------------
__global__ __launch_bounds__(1024) void compact_kernel(
    const int* __restrict__ mask, int* __restrict__ idx, int* __restrict__ cnt)
{
    __shared__ int wsum[32];
    __shared__ int stotal;
    const int b = blockIdx.x, t = threadIdx.x;
    const int* mb = mask + (size_t)b * NTOK;
    const int base4 = t * 4;
    int m0 = mb[base4 + 0] != 0, m1 = mb[base4 + 1] != 0;
    int m2 = mb[base4 + 2] != 0, m3 = mb[base4 + 3] != 0;
    const int s = m0 + m1 + m2 + m3;
    const int lane = t & 31, w = t >> 5;
    int inc = s;
#pragma unroll
    for (int o = 1; o < 32; o <<= 1) {
        int v = __shfl_up_sync(0xffffffffu, inc, o);
        if (lane >= o) inc += v;
    }
    if (lane == 31) wsum[w] = inc;
    __syncthreads();
    if (w == 0) {
        int v = wsum[lane];
#pragma unroll
        for (int o = 1; o < 32; o <<= 1) {
            int u = __shfl_up_sync(0xffffffffu, v, o);
            if (lane >= o) v += u;
        }
        wsum[lane] = v;
    }
    __syncthreads();
    const int basep = inc - s + (w ? wsum[w - 1] : 0);
    int* ib = idx + (size_t)b * PADK;
    int p = basep;
    if (m0) ib[p++] = base4 + 0;
    if (m1) ib[p++] = base4 + 1;
    if (m2) ib[p++] = base4 + 2;
    if (m3) ib[p++] = base4 + 3;
    if (t == 1023) stotal = basep + s;
    __syncthreads();
    const int total = stotal;
    if (t < NLAT) ib[total + t] = NTOK + t;
    for (int j = total + NLAT + t; j < PADK; j += 1024) ib[j] = NTOK;
    if (t == 0) cnt[b] = total + NLAT;
}

// ---------------- shared LN row body -> fp16 output ----------------
__device__ __forceinline__ void ln_row_h(const float* __restrict__ xr,
                                         const float* __restrict__ gamma,
                                         const float* __restrict__ beta,
                                         __half* __restrict__ outr)
{
    const int t = threadIdx.x;
    float4 v = ((const float4*)xr)[t];
    float s  = v.x + v.y + v.z + v.w;
    float ss = v.x*v.x + v.y*v.y + v.z*v.z + v.w*v.w;
#pragma unroll
    for (int o = 16; o; o >>= 1) {
        s  += __shfl_xor_sync(0xffffffffu, s, o);
        ss += __shfl_xor_sync(0xffffffffu, ss, o);
    }
    __shared__ float rs[8], rss[8];
    if ((t & 31) == 0) { rs[t >> 5] = s; rss[t >> 5] = ss; }
    __syncthreads();
    float sum = 0.f, sq = 0.f;
#pragma unroll
    for (int i = 0; i < 8; i++) { sum += rs[i]; sq += rss[i]; }
    const float mu  = sum * (1.f / DMODEL);
    const float inv = rsqrtf(sq * (1.f / DMODEL) - mu * mu + 1e-5f);
    float4 g  = ((const float4*)gamma)[t];
    float4 bb = ((const float4*)beta)[t];
    float ox = (v.x - mu) * inv * g.x + bb.x;
    float oy = (v.y - mu) * inv * g.y + bb.y;
    float oz = (v.z - mu) * inv * g.z + bb.z;
    float ow = (v.w - mu) * inv * g.w + bb.w;
    __half2* op = (__half2*)(outr + t * 4);
    op[0] = __floats2half2_rn(ox, oy);
    op[1] = __floats2half2_rn(oz, ow);
}

__global__ __launch_bounds__(256) void ln_dense(
    const float* __restrict__ in, const float* __restrict__ gamma,
    const float* __restrict__ beta, __half* __restrict__ out)
{
    const size_t row = blockIdx.x;
    ln_row_h(in + row * DMODEL, gamma, beta, out + row * DMODEL);
}

__global__ __launch_bounds__(256) void ln_gather(
    const float* __restrict__ x, const float* __restrict__ lat,
    const int* __restrict__ idx, const int* __restrict__ cnt,
    const float* __restrict__ g1, const float* __restrict__ b1,
    const float* __restrict__ g2, const float* __restrict__ b2,
    __half* __restrict__ out)
{
    const int b = blockIdx.y;
    const int slot = blockIdx.x;
    const int nk = cnt[b];
    if (slot >= ((nk + 127) & ~127)) return;
    const int g = idx[(size_t)b * PADK + slot];
    const float* src;
    const float *gam, *bet;
    if (g < NTOK) { src = x   + ((size_t)b * NTOK + g) * DMODEL;          gam = g1; bet = b1; }
    else          { src = lat + ((size_t)b * NLAT + (g - NTOK)) * DMODEL; gam = g2; bet = b2; }
    ln_row_h(src, gam, bet, out + ((size_t)b * PADK + slot) * DMODEL);
}

// ---------------- fp16 GEMM geometry ----------------
// smem rows: 40 halves (32 data + 8 pad) = 20 words; conflict-free fragment loads.
#define HBK  32                     // K halves per stage
#define HLD  20                     // words per smem row
#define HA_W (128 * HLD)            // A stage words (2560)

// ======== kv GEMM: 128x256 CTA tile, 8 warps (2m x 4n), warp 64x64 ========
#define HB_W   (256 * HLD)          // B stage words (5120)
#define HSTG_W (HA_W + HB_W)        // 7680 words = 30720 B
#define KV_SMEM (2 * HSTG_W * 4)    // 61440 B
#define KV_TILES (PADK / 128)       // 33

__global__ __launch_bounds__(256, 1) void gemm_kv_h(
    const __half* __restrict__ lnh, const __half* __restrict__ Bt,
    float* __restrict__ kv, const int* __restrict__ cnt)
{
    const int b    = blockIdx.y / KV_TILES;
    const int tile = blockIdx.y - b * KV_TILES;
    const int bm   = tile * 128;
    if (bm >= cnt[b]) return;

    const __half* A = lnh + ((size_t)b * PADK + bm) * DMODEL;
    float* C = kv + ((size_t)b * PADK + bm) * (2 * DMODEL);
    const int N = 2 * DMODEL;
    const int bn = blockIdx.x * 256;

    extern __shared__ uint32_t smw[];
    const int tid = threadIdx.x;
    const int warp = tid >> 5, lane = tid & 31;
    const int wm = (warp >> 2) * 64;
    const int wn = (warp & 3) * 64;
    const int g4 = lane >> 2, t4 = lane & 3;
    const uint32_t s_base = smem_u32(smw);

    float acc[4][8][4];
#pragma unroll
    for (int mi = 0; mi < 4; mi++)
#pragma unroll
        for (int ni = 0; ni < 8; ni++)
#pragma unroll
            for (int c = 0; c < 4; c++) acc[mi][ni][c] = 0.f;

    auto load_stage = [&](int st, int k0) {
        const uint32_t so = (uint32_t)(st * HSTG_W * 4);
#pragma unroll
        for (int j = 0; j < 2; j++) {          // A: 128 rows x 4 chunks of 8 halves
            int idx = tid + j * 256, r = idx >> 2, c = idx & 3;
            cp_async16(s_base + so + (uint32_t)((r * HLD + c * 4) * 4),
                       A + (size_t)r * DMODEL + k0 + c * 8);
        }
#pragma unroll
        for (int j = 0; j < 4; j++) {          // B: 256 rows x 4 chunks
            int idx = tid + j * 256, r = idx >> 2, c = idx & 3;
            cp_async16(s_base + so + (uint32_t)((HA_W + r * HLD + c * 4) * 4),
                       Bt + (size_t)(bn + r) * DMODEL + k0 + c * 8);
        }
        cp_commit();
    };

    load_stage(0, 0);
    const int KT = DMODEL / HBK;   // 32
    for (int kt = 0; kt < KT; kt++) {
        if (kt + 1 < KT) { load_stage((kt + 1) & 1, (kt + 1) * HBK); cp_wait1(); }
        else             { cp_wait0(); }
        __syncthreads();
        const uint32_t* as = smw + (kt & 1) * HSTG_W;
        const uint32_t* bs = as + HA_W;
#pragma unroll
        for (int kk = 0; kk < 2; kk++) {       // two k16 steps per 32-half stage
            uint32_t af[4][4];
#pragma unroll
            for (int mi = 0; mi < 4; mi++) {
                const uint32_t* ap = as + (wm + mi * 16 + g4) * HLD + kk * 8 + t4;
                af[mi][0] = ap[0];
                af[mi][1] = ap[8 * HLD];
                af[mi][2] = ap[4];
                af[mi][3] = ap[8 * HLD + 4];
            }
            uint32_t bf[8][2];
#pragma unroll
            for (int ni = 0; ni < 8; ni++) {
                const uint32_t* bp = bs + (wn + ni * 8 + g4) * HLD + kk * 8 + t4;
                bf[ni][0] = bp[0];
                bf[ni][1] = bp[4];
            }
#pragma unroll
            for (int mi = 0; mi < 4; mi++)
#pragma unroll
                for (int ni = 0; ni < 8; ni++)
                    mma16(acc[mi][ni], af[mi], bf[ni]);
        }
        __syncthreads();
    }

#pragma unroll
    for (int mi = 0; mi < 4; mi++) {
        int r0 = wm + mi * 16 + g4;
#pragma unroll
        for (int ni = 0; ni < 8; ni++) {
            int c0 = bn + wn + ni * 8 + t4 * 2;
            *(float2*)(C + (long long)r0 * N + c0)       = make_float2(acc[mi][ni][0], acc[mi][ni][1]);
            *(float2*)(C + (long long)(r0 + 8) * N + c0) = make_float2(acc[mi][ni][2], acc[mi][ni][3]);
        }
    }
}

// ======== small GEMM: 128x128 CTA tile, 8 warps (2m x 4n), warp 64x32; K=N=1024 ========
#define SB_W   (128 * HLD)
#define SSTG_W (HA_W + SB_W)        // 5120 words = 20480 B
#define SG_SMEM (2 * SSTG_W * 4)    // 40960 B

__global__ __launch_bounds__(256) void gemm_h(
    const __half* __restrict__ Ag, const __half* __restrict__ Bt, float* __restrict__ C)
{
    const __half* A = Ag + (size_t)(blockIdx.y * 128) * DMODEL;
    C += (size_t)(blockIdx.y * 128) * DMODEL;
    const int bn = blockIdx.x * 128;

    extern __shared__ uint32_t smw[];
    const int tid = threadIdx.x;
    const int warp = tid >> 5, lane = tid & 31;
    const int wm = (warp >> 2) * 64;
    const int wn = (warp & 3) * 32;
    const int g4 = lane >> 2, t4 = lane & 3;
    const uint32_t s_base = smem_u32(smw);

    float acc[4][4][4];
#pragma unroll
    for (int mi = 0; mi < 4; mi++)
#pragma unroll
        for (int ni = 0; ni < 4; ni++)
#pragma unroll
            for (int c = 0; c < 4; c++) acc[mi][ni][c] = 0.f;

    auto load_stage = [&](int st, int k0) {
        const uint32_t so = (uint32_t)(st * SSTG_W * 4);
#pragma unroll
        for (int j = 0; j < 2; j++) {
            int idx = tid + j * 256, r = idx >> 2, c = idx & 3;
            cp_async16(s_base + so + (uint32_t)((r * HLD + c * 4) * 4),
                       A + (size_t)r * DMODEL + k0 + c * 8);
        }
#pragma unroll
        for (int j = 0; j < 2; j++) {
            int idx = tid + j * 256, r = idx >> 2, c = idx & 3;
            cp_async16(s_base + so + (uint32_t)((HA_W + r * HLD + c * 4) * 4),
                       Bt + (size_t)(bn + r) * DMODEL + k0 + c * 8);
        }
        cp_commit();
    };

    load_stage(0, 0);
    const int KT = DMODEL / HBK;
    for (int kt = 0; kt < KT; kt++) {
        if (kt + 1 < KT) { load_stage((kt + 1) & 1, (kt + 1) * HBK); cp_wait1(); }
        else             { cp_wait0(); }
        __syncthreads();
        const uint32_t* as = smw + (kt & 1) * SSTG_W;
        const uint32_t* bs = as + HA_W;
#pragma unroll
        for (int kk = 0; kk < 2; kk++) {
            uint32_t af[4][4];
#pragma unroll
            for (int mi = 0; mi < 4; mi++) {
                const uint32_t* ap = as + (wm + mi * 16 + g4) * HLD + kk * 8 + t4;
                af[mi][0] = ap[0];
                af[mi][1] = ap[8 * HLD];
                af[mi][2] = ap[4];
                af[mi][3] = ap[8 * HLD + 4];
            }
            uint32_t bf[4][2];
#pragma unroll
            for (int ni = 0; ni < 4; ni++) {
                const uint32_t* bp = bs + (wn + ni * 8 + g4) * HLD + kk * 8 + t4;
                bf[ni][0] = bp[0];
                bf[ni][1] = bp[4];
            }
#pragma unroll
            for (int mi = 0; mi < 4; mi++)
#pragma unroll
                for (int ni = 0; ni < 4; ni++)
                    mma16(acc[mi][ni], af[mi], bf[ni]);
        }
        __syncthreads();
    }

#pragma unroll
    for (int mi = 0; mi < 4; mi++) {
        int r0 = wm + mi * 16 + g4;
#pragma unroll
        for (int ni = 0; ni < 4; ni++) {
            int c0 = bn + wn + ni * 8 + t4 * 2;
            *(float2*)(C + (long long)r0 * DMODEL + c0)       = make_float2(acc[mi][ni][0], acc[mi][ni][1]);
            *(float2*)(C + (long long)(r0 + 8) * DMODEL + c0) = make_float2(acc[mi][ni][2], acc[mi][ni][3]);
        }
    }
}

// ---------------- flash attention over compacted keys, one CTA per (b, h) ----------------
#define ATTN_SMEM ((3 * 64 * 68 + 64 * 65 + 64) * 4)

__global__ __launch_bounds__(256) void attn_kernel(
    const float* __restrict__ qb, const float* __restrict__ kv,
    const int* __restrict__ cnt, __half* __restrict__ atth)
{
    extern __shared__ float sh[];
    float* Qs = sh;
    float* Ks = Qs + 64 * 68;
    float* Vs = Ks + 64 * 68;
    float* Ps = Vs + 64 * 68;
    float* Mk = Ps + 64 * 65;

    const int tid = threadIdx.x;
    const int bh = blockIdx.x;
    const int b = bh >> 4, h = bh & (HEADS - 1);
    const int q = tid >> 2, sub = tid & 3;
    const int nk = cnt[b];
    const int nch = (nk + 63) >> 6;

#pragma unroll
    for (int j = 0; j < 4; j++) {
        int f = tid + j * 256;
        int r = f >> 4, c4 = f & 15;
        float4 v = *(const float4*)(qb + ((size_t)(b * NLAT + r)) * DMODEL + h * DH + c4 * 4);
        v.x *= 0.125f; v.y *= 0.125f; v.z *= 0.125f; v.w *= 0.125f;
        *(float4*)(Qs + r * 68 + c4 * 4) = v;
    }

    float4 Oa[4];
#pragma unroll
    for (int i = 0; i < 4; i++) Oa[i] = make_float4(0.f, 0.f, 0.f, 0.f);
    float mrun = -1e30f, lsum = 0.f;

    const float* kbase = kv + ((size_t)b * PADK) * 2048 + h * DH;

    for (int ch = 0; ch < nch; ch++) {
        const int j0 = ch * 64;
        __syncthreads();
#pragma unroll
        for (int j = 0; j < 4; j++) {
            int f = tid + j * 256;
            int r = f >> 4, c4 = f & 15;
            const float* rp = kbase + (size_t)(j0 + r) * 2048 + c4 * 4;
            *(float4*)(Ks + r * 68 + c4 * 4) = *(const float4*)rp;
            *(float4*)(Vs + r * 68 + c4 * 4) = *(const float4*)(rp + DMODEL);
        }
        if (tid < 64)
            Mk[tid] = (j0 + tid < nk) ? 1.f : 0.f;
        __syncthreads();

        float sreg[16];
#pragma unroll
        for (int jj = 0; jj < 16; jj++) sreg[jj] = 0.f;
#pragma unroll
        for (int d4 = 0; d4 < 16; d4++) {
            float4 qv = *(const float4*)(Qs + q * 68 + d4 * 4);
#pragma unroll
            for (int jj = 0; jj < 16; jj++) {
                float4 kvv = *(const float4*)(Ks + (4 * jj + sub) * 68 + d4 * 4);
                sreg[jj] += qv.x * kvv.x + qv.y * kvv.y + qv.z * kvv.z + qv.w * kvv.w;
            }
        }
#pragma unroll
        for (int jj = 0; jj < 16; jj++)
            if (!(Mk[4 * jj + sub] > 0.f)) sreg[jj] = -1e30f;

        float mloc = -1e30f;
#pragma unroll
        for (int jj = 0; jj < 16; jj++) mloc = fmaxf(mloc, sreg[jj]);
        mloc = fmaxf(mloc, __shfl_xor_sync(0xffffffffu, mloc, 1));
        mloc = fmaxf(mloc, __shfl_xor_sync(0xffffffffu, mloc, 2));
        float mnew = fmaxf(mrun, mloc);
        float corr = __expf(mrun - mnew);
        float psum = 0.f;
#pragma unroll
        for (int jj = 0; jj < 16; jj++) {
            int j = 4 * jj + sub;
            float p = __expf(sreg[jj] - mnew) * Mk[j];
            psum += p;
            Ps[q * 65 + j] = p;
        }
        psum += __shfl_xor_sync(0xffffffffu, psum, 1);
        psum += __shfl_xor_sync(0xffffffffu, psum, 2);
        lsum = lsum * corr + psum;
#pragma unroll
        for (int i = 0; i < 4; i++) { Oa[i].x *= corr; Oa[i].y *= corr; Oa[i].z *= corr; Oa[i].w *= corr; }
        mrun = mnew;
        __syncthreads();

#pragma unroll 4
        for (int j = 0; j < 64; j++) {
            float p = Ps[q * 65 + j];
#pragma unroll
            for (int d4 = 0; d4 < 4; d4++) {
                float4 v = *(const float4*)(Vs + j * 68 + d4 * 16 + sub * 4);
                Oa[d4].x += p * v.x; Oa[d4].y += p * v.y;
                Oa[d4].z += p * v.z; Oa[d4].w += p * v.w;
            }
        }
    }

    // fp16 output (feeds the fp16 out-projection GEMM)
    float rl = __fdividef(1.f, lsum);
    __half* orow = atth + ((size_t)(b * NLAT + q)) * DMODEL + h * DH;
#pragma unroll
    for (int d4 = 0; d4 < 4; d4++) {
        float4 v = Oa[d4];
        __half2* op = (__half2*)(orow + d4 * 16 + sub * 4);
        op[0] = __floats2half2_rn(v.x * rl, v.y * rl);
        op[1] = __floats2half2_rn(v.z * rl, v.w * rl);
    }
}

// ---------------- launch ----------------
extern "C" void kernel_launch(void* const* d_in, const int* in_sizes, int n_in,
                              void* d_out, int out_size)
{
    const float* x    = (const float*)d_in[0];
    const float* lat  = (const float*)d_in[1];
    const int*   mask = (const int*)d_in[2];
    const float* g1   = (const float*)d_in[3];
    const float* b1   = (const float*)d_in[4];
    const float* g2   = (const float*)d_in[5];
    const float* b2   = (const float*)d_in[6];
    const float* Wq   = (const float*)d_in[7];
    const float* Wkv  = (const float*)d_in[8];
    const float* Wout = (const float*)d_in[9];
    float* out = (float*)d_out;

    __half *lnhp, *lnlathp, *atthp, *whp;
    float *kvp, *qp;
    int *idxp, *cntp;
    cudaGetSymbolAddress((void**)&lnhp,    g_lnh);
    cudaGetSymbolAddress((void**)&kvp,     g_kv);
    cudaGetSymbolAddress((void**)&lnlathp, g_lnlath);
    cudaGetSymbolAddress((void**)&qp,      g_q);
    cudaGetSymbolAddress((void**)&atthp,   g_atth);
    cudaGetSymbolAddress((void**)&whp,     g_wh);
    cudaGetSymbolAddress((void**)&idxp,    g_idx);
    cudaGetSymbolAddress((void**)&cntp,    g_cnt);

    cudaFuncSetAttribute(gemm_kv_h,   cudaFuncAttributeMaxDynamicSharedMemorySize, KV_SMEM);
    cudaFuncSetAttribute(gemm_h,      cudaFuncAttributeMaxDynamicSharedMemorySize, SG_SMEM);
    cudaFuncSetAttribute(attn_kernel, cudaFuncAttributeMaxDynamicSharedMemorySize, ATTN_SMEM);

    // 0. transpose + fp16-convert weights (one-shot)
    transpose_h<<<dim3(2 * DMODEL / 32, DMODEL / 32), dim3(32, 8)>>>(Wkv,  whp + WH_KV,  DMODEL, 2 * DMODEL);
    transpose_h<<<dim3(DMODEL / 32, DMODEL / 32),     dim3(32, 8)>>>(Wq,   whp + WH_Q,   DMODEL, DMODEL);
    transpose_h<<<dim3(DMODEL / 32, DMODEL / 32),     dim3(32, 8)>>>(Wout, whp + WH_OUT, DMODEL, DMODEL);

    // 1. compact unmasked token indices (+ latents) per batch
    compact_kernel<<<BATCH, 1024>>>(mask, idxp, cntp);

    // 2. LN(latents) dense (for q), fp16
    ln_dense<<<BATCH * NLAT, 256>>>(lat, g2, b2, lnlathp);

    // 3. LN in compacted key order, fp16
    ln_gather<<<dim3(PADK, BATCH), 256>>>(x, lat, idxp, cntp, g1, b1, g2, b2, lnhp);

    // 4. kv = ln_compact @ Wkv   (fp16 mma, 128x256 tiles)
    gemm_kv_h<<<dim3(2 * DMODEL / 256, BATCH * KV_TILES), 256, KV_SMEM>>>(
        lnhp, whp + WH_KV, kvp, cntp);

    // 5. q = LN(latents) @ Wq  (fp16 mma)
    gemm_h<<<dim3(DMODEL / 128, (BATCH * NLAT) / 128), 256, SG_SMEM>>>(
        lnlathp, whp + WH_Q, qp);

    // 6. attention over compacted keys (fp32 math, fp16 out)
    attn_kernel<<<BATCH * HEADS, 256, ATTN_SMEM>>>(qp, kvp, cntp, atthp);

    // 7. out = att @ Wout  (fp16 mma, fp32 out)
    gemm_h<<<dim3(DMODEL / 128, (BATCH * NLAT) / 128), 256, SG_SMEM>>>(
        atthp, whp + WH_OUT, out);
}

// round 13
// speedup vs baseline: 3.6090x; 1.6001x over previous
#include <cuda_runtime.h>
#include <cuda_fp16.h>
#include <cstdint>

#define BATCH 8
#define NTOK 4096
#define NLAT 64
#define PADK 4224              // padded compacted-key capacity per batch (33 * 128)
#define DMODEL 1024
#define HEADS 16
#define DH 64

// ---------------- scratch (static device memory; no allocations) ----------------
__device__ __half g_lnh   [(size_t)BATCH * PADK * DMODEL];     // LN rows, compacted order, fp16
__device__ __half g_kvh   [(size_t)BATCH * PADK * 2 * DMODEL]; // [b, slot, 2048] : k | v (fp16)
__device__ __half g_lnlath[(size_t)BATCH * NLAT * DMODEL];     // dense LN(latents), fp16
__device__ float  g_q     [(size_t)BATCH * NLAT * DMODEL];     // fp32
__device__ __half g_atth  [(size_t)BATCH * NLAT * DMODEL];     // attention out, fp16
__device__ int    g_idx   [(size_t)BATCH * PADK];
__device__ int    g_cnt   [BATCH];
// fp16 transposed weights ([n][k]-major): WkvT (2048x1024) | WqT (1024x1024) | WoutT (1024x1024)
__device__ __half g_wh    [(size_t)4 * DMODEL * DMODEL];
#define WH_KV   0
#define WH_Q    ((size_t)2 * DMODEL * DMODEL)
#define WH_OUT  ((size_t)3 * DMODEL * DMODEL)

// ---------------- helpers ----------------
__device__ __forceinline__ uint32_t smem_u32(const void* p) {
    uint32_t a;
    asm("{ .reg .u64 t; cvta.to.shared.u64 t, %1; cvt.u32.u64 %0, t; }" : "=r"(a) : "l"(p));
    return a;
}
__device__ __forceinline__ void cp_async16(uint32_t s, const void* g) {
    asm volatile("cp.async.cg.shared.global [%0], [%1], 16;\n" :: "r"(s), "l"(g));
}
__device__ __forceinline__ void cp_commit() { asm volatile("cp.async.commit_group;\n" ::); }
__device__ __forceinline__ void cp_wait0()  { asm volatile("cp.async.wait_group 0;\n" ::); }
__device__ __forceinline__ void cp_wait1()  { asm volatile("cp.async.wait_group 1;\n" ::); }

// fp16 mma: D(16x8,f32) += A(16x16,f16) * B(16x8,f16)
__device__ __forceinline__ void mma16(float* d, const uint32_t* a, const uint32_t* b) {
    asm volatile(
        "mma.sync.aligned.m16n8k16.row.col.f32.f16.f16.f32 "
        "{%0,%1,%2,%3}, {%4,%5,%6,%7}, {%8,%9}, {%0,%1,%2,%3};\n"
        : "+f"(d[0]), "+f"(d[1]), "+f"(d[2]), "+f"(d[3])
        : "r"(a[0]), "r"(a[1]), "r"(a[2]), "r"(a[3]), "r"(b[0]), "r"(b[1]));
}

// ---------------- one-shot weight transpose+convert: [K][N] f32 -> [N][K] f16 ----------------
__global__ __launch_bounds__(256) void transpose_h(
    const float* __restrict__ in, __half* __restrict__ out, int K, int N)
{
    __shared__ float t[32][33];
    const int tx = threadIdx.x, ty = threadIdx.y;
    const int x  = blockIdx.x * 32 + tx;      // n
    const int y0 = blockIdx.y * 32;           // k
#pragma unroll
    for (int i = ty; i < 32; i += 8)
        t[i][tx] = in[(size_t)(y0 + i) * N + x];
    __syncthreads();
    const int ox  = blockIdx.y * 32 + tx;     // k
    const int oy0 = blockIdx.x * 32;          // n
#pragma unroll
    for (int i = ty; i < 32; i += 8)
        out[(size_t)(oy0 + i) * K + ox] = __float2half_rn(t[tx][i]);
}

// ---------------- mask compaction: deterministic block prefix-sum ----------------
__global__ __launch_bounds__(1024) void compact_kernel(
    const int* __restrict__ mask, int* __restrict__ idx, int* __restrict__ cnt)
{
    __shared__ int wsum[32];
    __shared__ int stotal;
    const int b = blockIdx.x, t = threadIdx.x;
    const int* mb = mask + (size_t)b * NTOK;
    const int base4 = t * 4;
    int m0 = mb[base4 + 0] != 0, m1 = mb[base4 + 1] != 0;
    int m2 = mb[base4 + 2] != 0, m3 = mb[base4 + 3] != 0;
    const int s = m0 + m1 + m2 + m3;
    const int lane = t & 31, w = t >> 5;
    int inc = s;
#pragma unroll
    for (int o = 1; o < 32; o <<= 1) {
        int v = __shfl_up_sync(0xffffffffu, inc, o);
        if (lane >= o) inc += v;
    }
    if (lane == 31) wsum[w] = inc;
    __syncthreads();
    if (w == 0) {
        int v = wsum[lane];
#pragma unroll
        for (int o = 1; o < 32; o <<= 1) {
            int u = __shfl_up_sync(0xffffffffu, v, o);
            if (lane >= o) v += u;
        }
        wsum[lane] = v;
    }
    __syncthreads();
    const int basep = inc - s + (w ? wsum[w - 1] : 0);
    int* ib = idx + (size_t)b * PADK;
    int p = basep;
    if (m0) ib[p++] = base4 + 0;
    if (m1) ib[p++] = base4 + 1;
    if (m2) ib[p++] = base4 + 2;
    if (m3) ib[p++] = base4 + 3;
    if (t == 1023) stotal = basep + s;
    __syncthreads();
    const int total = stotal;
    if (t < NLAT) ib[total + t] = NTOK + t;
    for (int j = total + NLAT + t; j < PADK; j += 1024) ib[j] = NTOK;
    if (t == 0) cnt[b] = total + NLAT;
}

// ---------------- shared LN row body -> fp16 output ----------------
__device__ __forceinline__ void ln_row_h(const float* __restrict__ xr,
                                         const float* __restrict__ gamma,
                                         const float* __restrict__ beta,
                                         __half* __restrict__ outr)
{
    const int t = threadIdx.x;
    float4 v = ((const float4*)xr)[t];
    float s  = v.x + v.y + v.z + v.w;
    float ss = v.x*v.x + v.y*v.y + v.z*v.z + v.w*v.w;
#pragma unroll
    for (int o = 16; o; o >>= 1) {
        s  += __shfl_xor_sync(0xffffffffu, s, o);
        ss += __shfl_xor_sync(0xffffffffu, ss, o);
    }
    __shared__ float rs[8], rss[8];
    if ((t & 31) == 0) { rs[t >> 5] = s; rss[t >> 5] = ss; }
    __syncthreads();
    float sum = 0.f, sq = 0.f;
#pragma unroll
    for (int i = 0; i < 8; i++) { sum += rs[i]; sq += rss[i]; }
    const float mu  = sum * (1.f / DMODEL);
    const float inv = rsqrtf(sq * (1.f / DMODEL) - mu * mu + 1e-5f);
    float4 g  = ((const float4*)gamma)[t];
    float4 bb = ((const float4*)beta)[t];
    float ox = (v.x - mu) * inv * g.x + bb.x;
    float oy = (v.y - mu) * inv * g.y + bb.y;
    float oz = (v.z - mu) * inv * g.z + bb.z;
    float ow = (v.w - mu) * inv * g.w + bb.w;
    __half2* op = (__half2*)(outr + t * 4);
    op[0] = __floats2half2_rn(ox, oy);
    op[1] = __floats2half2_rn(oz, ow);
}

__global__ __launch_bounds__(256) void ln_dense(
    const float* __restrict__ in, const float* __restrict__ gamma,
    const float* __restrict__ beta, __half* __restrict__ out)
{
    const size_t row = blockIdx.x;
    ln_row_h(in + row * DMODEL, gamma, beta, out + row * DMODEL);
}

__global__ __launch_bounds__(256) void ln_gather(
    const float* __restrict__ x, const float* __restrict__ lat,
    const int* __restrict__ idx, const int* __restrict__ cnt,
    const float* __restrict__ g1, const float* __restrict__ b1,
    const float* __restrict__ g2, const float* __restrict__ b2,
    __half* __restrict__ out)
{
    const int b = blockIdx.y;
    const int slot = blockIdx.x;
    const int nk = cnt[b];
    if (slot >= ((nk + 127) & ~127)) return;
    const int g = idx[(size_t)b * PADK + slot];
    const float* src;
    const float *gam, *bet;
    if (g < NTOK) { src = x   + ((size_t)b * NTOK + g) * DMODEL;          gam = g1; bet = b1; }
    else          { src = lat + ((size_t)b * NLAT + (g - NTOK)) * DMODEL; gam = g2; bet = b2; }
    ln_row_h(src, gam, bet, out + ((size_t)b * PADK + slot) * DMODEL);
}

// ---------------- fp16 GEMM geometry ----------------
#define HBK  32                     // K halves per stage
#define HLD  20                     // words per smem row (32 data halves + 8 pad)
#define HA_W (128 * HLD)            // A stage words (2560)

// ======== kv GEMM: 128x256 CTA tile, 8 warps (2m x 4n), warp 64x64; fp16 OUT ========
#define HB_W   (256 * HLD)
#define HSTG_W (HA_W + HB_W)        // 7680 words
#define KV_SMEM (2 * HSTG_W * 4)    // 61440 B
#define KV_TILES (PADK / 128)       // 33

__global__ __launch_bounds__(256, 1) void gemm_kv_h(
    const __half* __restrict__ lnh, const __half* __restrict__ Bt,
    __half* __restrict__ kvh, const int* __restrict__ cnt)
{
    const int b    = blockIdx.y / KV_TILES;
    const int tile = blockIdx.y - b * KV_TILES;
    const int bm   = tile * 128;
    if (bm >= cnt[b]) return;

    const __half* A = lnh + ((size_t)b * PADK + bm) * DMODEL;
    __half* C = kvh + ((size_t)b * PADK + bm) * (2 * DMODEL);
    const int N = 2 * DMODEL;
    const int bn = blockIdx.x * 256;

    extern __shared__ uint32_t smw[];
    const int tid = threadIdx.x;
    const int warp = tid >> 5, lane = tid & 31;
    const int wm = (warp >> 2) * 64;
    const int wn = (warp & 3) * 64;
    const int g4 = lane >> 2, t4 = lane & 3;
    const uint32_t s_base = smem_u32(smw);

    float acc[4][8][4];
#pragma unroll
    for (int mi = 0; mi < 4; mi++)
#pragma unroll
        for (int ni = 0; ni < 8; ni++)
#pragma unroll
            for (int c = 0; c < 4; c++) acc[mi][ni][c] = 0.f;

    auto load_stage = [&](int st, int k0) {
        const uint32_t so = (uint32_t)(st * HSTG_W * 4);
#pragma unroll
        for (int j = 0; j < 2; j++) {
            int idx = tid + j * 256, r = idx >> 2, c = idx & 3;
            cp_async16(s_base + so + (uint32_t)((r * HLD + c * 4) * 4),
                       A + (size_t)r * DMODEL + k0 + c * 8);
        }
#pragma unroll
        for (int j = 0; j < 4; j++) {
            int idx = tid + j * 256, r = idx >> 2, c = idx & 3;
            cp_async16(s_base + so + (uint32_t)((HA_W + r * HLD + c * 4) * 4),
                       Bt + (size_t)(bn + r) * DMODEL + k0 + c * 8);
        }
        cp_commit();
    };

    load_stage(0, 0);
    const int KT = DMODEL / HBK;   // 32
    for (int kt = 0; kt < KT; kt++) {
        if (kt + 1 < KT) { load_stage((kt + 1) & 1, (kt + 1) * HBK); cp_wait1(); }
        else             { cp_wait0(); }
        __syncthreads();
        const uint32_t* as = smw + (kt & 1) * HSTG_W;
        const uint32_t* bs = as + HA_W;
#pragma unroll
        for (int kk = 0; kk < 2; kk++) {
            uint32_t af[4][4];
#pragma unroll
            for (int mi = 0; mi < 4; mi++) {
                const uint32_t* ap = as + (wm + mi * 16 + g4) * HLD + kk * 8 + t4;
                af[mi][0] = ap[0];
                af[mi][1] = ap[8 * HLD];
                af[mi][2] = ap[4];
                af[mi][3] = ap[8 * HLD + 4];
            }
            uint32_t bf[8][2];
#pragma unroll
            for (int ni = 0; ni < 8; ni++) {
                const uint32_t* bp = bs + (wn + ni * 8 + g4) * HLD + kk * 8 + t4;
                bf[ni][0] = bp[0];
                bf[ni][1] = bp[4];
            }
#pragma unroll
            for (int mi = 0; mi < 4; mi++)
#pragma unroll
                for (int ni = 0; ni < 8; ni++)
                    mma16(acc[mi][ni], af[mi], bf[ni]);
        }
        __syncthreads();
    }

#pragma unroll
    for (int mi = 0; mi < 4; mi++) {
        int r0 = wm + mi * 16 + g4;
#pragma unroll
        for (int ni = 0; ni < 8; ni++) {
            int c0 = bn + wn + ni * 8 + t4 * 2;
            *(__half2*)(C + (size_t)r0 * N + c0)       = __floats2half2_rn(acc[mi][ni][0], acc[mi][ni][1]);
            *(__half2*)(C + (size_t)(r0 + 8) * N + c0) = __floats2half2_rn(acc[mi][ni][2], acc[mi][ni][3]);
        }
    }
}

// ======== small GEMM: 128x128 CTA tile, warp 64x32; K=N=1024, fp32 OUT ========
#define SB_W   (128 * HLD)
#define SSTG_W (HA_W + SB_W)
#define SG_SMEM (2 * SSTG_W * 4)

__global__ __launch_bounds__(256) void gemm_h(
    const __half* __restrict__ Ag, const __half* __restrict__ Bt, float* __restrict__ C)
{
    const __half* A = Ag + (size_t)(blockIdx.y * 128) * DMODEL;
    C += (size_t)(blockIdx.y * 128) * DMODEL;
    const int bn = blockIdx.x * 128;

    extern __shared__ uint32_t smw[];
    const int tid = threadIdx.x;
    const int warp = tid >> 5, lane = tid & 31;
    const int wm = (warp >> 2) * 64;
    const int wn = (warp & 3) * 32;
    const int g4 = lane >> 2, t4 = lane & 3;
    const uint32_t s_base = smem_u32(smw);

    float acc[4][4][4];
#pragma unroll
    for (int mi = 0; mi < 4; mi++)
#pragma unroll
        for (int ni = 0; ni < 4; ni++)
#pragma unroll
            for (int c = 0; c < 4; c++) acc[mi][ni][c] = 0.f;

    auto load_stage = [&](int st, int k0) {
        const uint32_t so = (uint32_t)(st * SSTG_W * 4);
#pragma unroll
        for (int j = 0; j < 2; j++) {
            int idx = tid + j * 256, r = idx >> 2, c = idx & 3;
            cp_async16(s_base + so + (uint32_t)((r * HLD + c * 4) * 4),
                       A + (size_t)r * DMODEL + k0 + c * 8);
        }
#pragma unroll
        for (int j = 0; j < 2; j++) {
            int idx = tid + j * 256, r = idx >> 2, c = idx & 3;
            cp_async16(s_base + so + (uint32_t)((HA_W + r * HLD + c * 4) * 4),
                       Bt + (size_t)(bn + r) * DMODEL + k0 + c * 8);
        }
        cp_commit();
    };

    load_stage(0, 0);
    const int KT = DMODEL / HBK;
    for (int kt = 0; kt < KT; kt++) {
        if (kt + 1 < KT) { load_stage((kt + 1) & 1, (kt + 1) * HBK); cp_wait1(); }
        else             { cp_wait0(); }
        __syncthreads();
        const uint32_t* as = smw + (kt & 1) * SSTG_W;
        const uint32_t* bs = as + HA_W;
#pragma unroll
        for (int kk = 0; kk < 2; kk++) {
            uint32_t af[4][4];
#pragma unroll
            for (int mi = 0; mi < 4; mi++) {
                const uint32_t* ap = as + (wm + mi * 16 + g4) * HLD + kk * 8 + t4;
                af[mi][0] = ap[0];
                af[mi][1] = ap[8 * HLD];
                af[mi][2] = ap[4];
                af[mi][3] = ap[8 * HLD + 4];
            }
            uint32_t bf[4][2];
#pragma unroll
            for (int ni = 0; ni < 4; ni++) {
                const uint32_t* bp = bs + (wn + ni * 8 + g4) * HLD + kk * 8 + t4;
                bf[ni][0] = bp[0];
                bf[ni][1] = bp[4];
            }
#pragma unroll
            for (int mi = 0; mi < 4; mi++)
#pragma unroll
                for (int ni = 0; ni < 4; ni++)
                    mma16(acc[mi][ni], af[mi], bf[ni]);
        }
        __syncthreads();
    }

#pragma unroll
    for (int mi = 0; mi < 4; mi++) {
        int r0 = wm + mi * 16 + g4;
#pragma unroll
        for (int ni = 0; ni < 4; ni++) {
            int c0 = bn + wn + ni * 8 + t4 * 2;
            *(float2*)(C + (long long)r0 * DMODEL + c0)       = make_float2(acc[mi][ni][0], acc[mi][ni][1]);
            *(float2*)(C + (long long)(r0 + 8) * DMODEL + c0) = make_float2(acc[mi][ni][2], acc[mi][ni][3]);
        }
    }
}

// ---------------- fp16 mma flash attention, one CTA per (b, h) ----------------
// smem word map (rows of 72 halves = 36 words; conflict-free per mod-32 algebra)
#define AW_Q   0
#define AW_K   2304              // 2 stages of 2304
#define AW_V   (2304 * 3)        // 2 stages
#define AW_T   (2304 * 5)        // V transposed [d][key]
#define AW_P   (2304 * 6)        // P fp16 [q][key]
#define AW_PS  (2304 * 7)        // S fp32 [64][68]
#define AW_MK  (AW_PS + 64 * 68)
#define AW_CR  (AW_MK + 64)
#define ATTN_SMEM2 ((AW_CR + 64) * 4)   // 82432 B

__global__ __launch_bounds__(256) void attn_mma(
    const float* __restrict__ qb, const __half* __restrict__ kvh,
    const int* __restrict__ cnt, __half* __restrict__ atth)
{
    extern __shared__ uint32_t aw[];
    __half* Qh = (__half*)(aw + AW_Q);
    __half* Vt = (__half*)(aw + AW_T);
    __half* Ph = (__half*)(aw + AW_P);
    float* Ps = (float*)(aw + AW_PS);
    float* Mk = (float*)(aw + AW_MK);
    float* Cr = (float*)(aw + AW_CR);

    const int tid = threadIdx.x;
    const int w = tid >> 5, lane = tid & 31;
    const int g4 = lane >> 2, t4 = lane & 3;
    const int wm = (w >> 2) * 32, wn = (w & 3) * 16;
    const int b = blockIdx.x >> 4, h = blockIdx.x & 15;
    const int nk = cnt[b];
    const int nch = (nk + 63) >> 6;
    const uint32_t s_base = smem_u32(aw);
    const int q = tid >> 2, sub = tid & 3;

    // Q: 64x64 f32 -> fp16 with 1/8 scale folded in
    {
        const int r = tid >> 2, c0 = (tid & 3) * 16;
        const float* src = qb + ((size_t)(b * NLAT + r)) * DMODEL + h * DH + c0;
        __half2* dst = (__half2*)(Qh + r * 72 + c0);
#pragma unroll
        for (int i = 0; i < 4; i++) {
            float4 v = ((const float4*)src)[i];
            dst[i * 2 + 0] = __floats2half2_rn(v.x * 0.125f, v.y * 0.125f);
            dst[i * 2 + 1] = __floats2half2_rn(v.z * 0.125f, v.w * 0.125f);
        }
    }

    float oa[2][2][4];
#pragma unroll
    for (int mi = 0; mi < 2; mi++)
#pragma unroll
        for (int ni = 0; ni < 2; ni++)
#pragma unroll
            for (int c = 0; c < 4; c++) oa[mi][ni][c] = 0.f;
    float mrun = -1e30f, lsum = 0.f;

    const __half* kb = kvh + ((size_t)b * PADK) * 2048 + h * DH;

    auto stage = [&](int ch) {
        const int st = ch & 1, j0 = ch * 64;
#pragma unroll
        for (int j = 0; j < 2; j++) {
            int idx = tid + j * 256, r = idx >> 3, c = idx & 7;
            const __half* s = kb + (size_t)(j0 + r) * 2048 + c * 8;
            cp_async16(s_base + (uint32_t)((AW_K + st * 2304 + r * 36 + c * 4) * 4), s);
            cp_async16(s_base + (uint32_t)((AW_V + st * 2304 + r * 36 + c * 4) * 4), s + 1024);
        }
        cp_commit();
    };

    stage(0);
    __syncthreads();   // Qh visible to all warps

    for (int ch = 0; ch < nch; ch++) {
        const int st = ch & 1;
        if (ch + 1 < nch) { stage(ch + 1); cp_wait1(); }
        else              { cp_wait0(); }
        __syncthreads();                                  // K/V(st) staged; prev chunk consumers done

        if (tid < 64) Mk[tid] = (ch * 64 + tid < nk) ? 1.f : 0.f;
        // transpose V(st) -> Vt [d][key]
        {
            const int key = tid >> 2, c0 = (tid & 3) * 16;
            const __half* vs = (const __half*)(aw + AW_V + st * 2304) + key * 72 + c0;
#pragma unroll
            for (int i = 0; i < 16; i++)
                Vt[(c0 + i) * 72 + key] = vs[i];
        }

        // S = Q @ K^T
        const uint32_t* Qw = aw + AW_Q;
        const uint32_t* Kw = aw + AW_K + st * 2304;
        float sc[2][2][4];
#pragma unroll
        for (int mi = 0; mi < 2; mi++)
#pragma unroll
            for (int ni = 0; ni < 2; ni++)
#pragma unroll
                for (int c = 0; c < 4; c++) sc[mi][ni][c] = 0.f;
#pragma unroll
        for (int ks = 0; ks < 4; ks++) {
            uint32_t af[2][4];
#pragma unroll
            for (int mi = 0; mi < 2; mi++) {
                const uint32_t* ap = Qw + (wm + mi * 16 + g4) * 36 + ks * 8 + t4;
                af[mi][0] = ap[0];
                af[mi][1] = ap[8 * 36];
                af[mi][2] = ap[4];
                af[mi][3] = ap[8 * 36 + 4];
            }
            uint32_t bf[2][2];
#pragma unroll
            for (int ni = 0; ni < 2; ni++) {
                const uint32_t* bp = Kw + (wn + ni * 8 + g4) * 36 + ks * 8 + t4;
                bf[ni][0] = bp[0];
                bf[ni][1] = bp[4];
            }
#pragma unroll
            for (int mi = 0; mi < 2; mi++)
#pragma unroll
                for (int ni = 0; ni < 2; ni++)
                    mma16(sc[mi][ni], af[mi], bf[ni]);
        }
#pragma unroll
        for (int mi = 0; mi < 2; mi++) {
            int r0 = wm + mi * 16 + g4;
#pragma unroll
            for (int ni = 0; ni < 2; ni++) {
                int c0 = wn + ni * 8 + t4 * 2;
                *(float2*)(Ps + r0 * 68 + c0)       = make_float2(sc[mi][ni][0], sc[mi][ni][1]);
                *(float2*)(Ps + (r0 + 8) * 68 + c0) = make_float2(sc[mi][ni][2], sc[mi][ni][3]);
            }
        }
        __syncthreads();                                  // S + Mk + Vt ready

        // online softmax (proven scalar structure, reading Ps)
        float sreg[16];
#pragma unroll
        for (int jj = 0; jj < 16; jj++) {
            sreg[jj] = Ps[q * 68 + 4 * jj + sub];
            if (!(Mk[4 * jj + sub] > 0.f)) sreg[jj] = -1e30f;
        }
        float mloc = -1e30f;
#pragma unroll
        for (int jj = 0; jj < 16; jj++) mloc = fmaxf(mloc, sreg[jj]);
        mloc = fmaxf(mloc, __shfl_xor_sync(0xffffffffu, mloc, 1));
        mloc = fmaxf(mloc, __shfl_xor_sync(0xffffffffu, mloc, 2));
        float mnew = fmaxf(mrun, mloc);
        float corr = __expf(mrun - mnew);
        float psum = 0.f;
#pragma unroll
        for (int jj = 0; jj < 16; jj++) {
            int j = 4 * jj + sub;
            float p = __expf(sreg[jj] - mnew) * Mk[j];
            psum += p;
            Ph[q * 72 + j] = __float2half_rn(p);
        }
        psum += __shfl_xor_sync(0xffffffffu, psum, 1);
        psum += __shfl_xor_sync(0xffffffffu, psum, 2);
        lsum = lsum * corr + psum;
        if (sub == 0) Cr[q] = corr;
        mrun = mnew;
        __syncthreads();                                  // Ph + Cr ready

        // O = O*corr + P @ V  (A = Ph, B = Vt)
        const uint32_t* Pw = aw + AW_P;
        const uint32_t* Tw = aw + AW_T;
#pragma unroll
        for (int mi = 0; mi < 2; mi++) {
            const float cr0 = Cr[wm + mi * 16 + g4];
            const float cr1 = Cr[wm + mi * 16 + g4 + 8];
#pragma unroll
            for (int ni = 0; ni < 2; ni++) {
                oa[mi][ni][0] *= cr0; oa[mi][ni][1] *= cr0;
                oa[mi][ni][2] *= cr1; oa[mi][ni][3] *= cr1;
            }
        }
#pragma unroll
        for (int ks = 0; ks < 4; ks++) {
            uint32_t af[2][4];
#pragma unroll
            for (int mi = 0; mi < 2; mi++) {
                const uint32_t* ap = Pw + (wm + mi * 16 + g4) * 36 + ks * 8 + t4;
                af[mi][0] = ap[0];
                af[mi][1] = ap[8 * 36];
                af[mi][2] = ap[4];
                af[mi][3] = ap[8 * 36 + 4];
            }
            uint32_t bf[2][2];
#pragma unroll
            for (int ni = 0; ni < 2; ni++) {
                const uint32_t* bp = Tw + (wn + ni * 8 + g4) * 36 + ks * 8 + t4;
                bf[ni][0] = bp[0];
                bf[ni][1] = bp[4];
            }
#pragma unroll
            for (int mi = 0; mi < 2; mi++)
#pragma unroll
                for (int ni = 0; ni < 2; ni++)
                    mma16(oa[mi][ni], af[mi], bf[ni]);
        }
        __syncthreads();                                  // protect Vt/Ph/Kh/Vh for next chunk
    }

    // normalize and store (fp16, feeds out-projection GEMM)
    if (sub == 0) Cr[q] = __fdividef(1.f, lsum);
    __syncthreads();
#pragma unroll
    for (int mi = 0; mi < 2; mi++) {
        int r0 = wm + mi * 16 + g4;
        float rl0 = Cr[r0], rl1 = Cr[r0 + 8];
#pragma unroll
        for (int ni = 0; ni < 2; ni++) {
            int c0 = wn + ni * 8 + t4 * 2;
            *(__half2*)(atth + ((size_t)(b * NLAT + r0)) * DMODEL + h * DH + c0) =
                __floats2half2_rn(oa[mi][ni][0] * rl0, oa[mi][ni][1] * rl0);
            *(__half2*)(atth + ((size_t)(b * NLAT + r0 + 8)) * DMODEL + h * DH + c0) =
                __floats2half2_rn(oa[mi][ni][2] * rl1, oa[mi][ni][3] * rl1);
        }
    }
}

// ---------------- launch ----------------
extern "C" void kernel_launch(void* const* d_in, const int* in_sizes, int n_in,
                              void* d_out, int out_size)
{
    const float* x    = (const float*)d_in[0];
    const float* lat  = (const float*)d_in[1];
    const int*   mask = (const int*)d_in[2];
    const float* g1   = (const float*)d_in[3];
    const float* b1   = (const float*)d_in[4];
    const float* g2   = (const float*)d_in[5];
    const float* b2   = (const float*)d_in[6];
    const float* Wq   = (const float*)d_in[7];
    const float* Wkv  = (const float*)d_in[8];
    const float* Wout = (const float*)d_in[9];
    float* out = (float*)d_out;

    __half *lnhp, *lnlathp, *atthp, *whp, *kvhp;
    float *qp;
    int *idxp, *cntp;
    cudaGetSymbolAddress((void**)&lnhp,    g_lnh);
    cudaGetSymbolAddress((void**)&kvhp,    g_kvh);
    cudaGetSymbolAddress((void**)&lnlathp, g_lnlath);
    cudaGetSymbolAddress((void**)&qp,      g_q);
    cudaGetSymbolAddress((void**)&atthp,   g_atth);
    cudaGetSymbolAddress((void**)&whp,     g_wh);
    cudaGetSymbolAddress((void**)&idxp,    g_idx);
    cudaGetSymbolAddress((void**)&cntp,    g_cnt);

    cudaFuncSetAttribute(gemm_kv_h, cudaFuncAttributeMaxDynamicSharedMemorySize, KV_SMEM);
    cudaFuncSetAttribute(gemm_h,    cudaFuncAttributeMaxDynamicSharedMemorySize, SG_SMEM);
    cudaFuncSetAttribute(attn_mma,  cudaFuncAttributeMaxDynamicSharedMemorySize, ATTN_SMEM2);

    // 0. transpose + fp16-convert weights (one-shot)
    transpose_h<<<dim3(2 * DMODEL / 32, DMODEL / 32), dim3(32, 8)>>>(Wkv,  whp + WH_KV,  DMODEL, 2 * DMODEL);
    transpose_h<<<dim3(DMODEL / 32, DMODEL / 32),     dim3(32, 8)>>>(Wq,   whp + WH_Q,   DMODEL, DMODEL);
    transpose_h<<<dim3(DMODEL / 32, DMODEL / 32),     dim3(32, 8)>>>(Wout, whp + WH_OUT, DMODEL, DMODEL);

    // 1. compact unmasked token indices (+ latents) per batch
    compact_kernel<<<BATCH, 1024>>>(mask, idxp, cntp);

    // 2. LN(latents) dense (for q), fp16
    ln_dense<<<BATCH * NLAT, 256>>>(lat, g2, b2, lnlathp);

    // 3. LN in compacted key order, fp16
    ln_gather<<<dim3(PADK, BATCH), 256>>>(x, lat, idxp, cntp, g1, b1, g2, b2, lnhp);

    // 4. kv = ln_compact @ Wkv   (fp16 mma, fp16 out)
    gemm_kv_h<<<dim3(2 * DMODEL / 256, BATCH * KV_TILES), 256, KV_SMEM>>>(
        lnhp, whp + WH_KV, kvhp, cntp);

    // 5. q = LN(latents) @ Wq  (fp16 mma, fp32 out)
    gemm_h<<<dim3(DMODEL / 128, (BATCH * NLAT) / 128), 256, SG_SMEM>>>(
        lnlathp, whp + WH_Q, qp);

    // 6. attention (fp16 mma S and PV, fp32 softmax)
    attn_mma<<<BATCH * HEADS, 256, ATTN_SMEM2>>>(qp, kvhp, cntp, atthp);

    // 7. out = att @ Wout  (fp16 mma, fp32 out)
    gemm_h<<<dim3(DMODEL / 128, (BATCH * NLAT) / 128), 256, SG_SMEM>>>(
        atthp, whp + WH_OUT, out);
}

// round 15
// speedup vs baseline: 3.6856x; 1.0212x over previous
#include <cuda_runtime.h>
#include <cuda_fp16.h>
#include <cstdint>

#define BATCH 8
#define NTOK 4096
#define NLAT 64
#define PADK 4224              // padded compacted-key capacity per batch (33 * 128)
#define DMODEL 1024
#define HEADS 16
#define DH 64

// ---------------- scratch (static device memory; no allocations) ----------------
__device__ __half g_lnh   [(size_t)BATCH * PADK * DMODEL];     // LN rows, compacted order, fp16
__device__ __half g_kvh   [(size_t)BATCH * HEADS * PADK * 2 * DH]; // [b][h][slot][k64|v64] fp16
__device__ __half g_lnlath[(size_t)BATCH * NLAT * DMODEL];     // dense LN(latents), fp16
__device__ float  g_q     [(size_t)BATCH * NLAT * DMODEL];     // fp32
__device__ __half g_atth  [(size_t)BATCH * NLAT * DMODEL];     // attention out, fp16
__device__ int    g_idx   [(size_t)BATCH * PADK];
__device__ int    g_cnt   [BATCH];
// fp16 transposed weights ([n][k]-major): WkvT (2048x1024) | WqT (1024x1024) | WoutT (1024x1024)
__device__ __half g_wh    [(size_t)4 * DMODEL * DMODEL];
#define WH_KV   0
#define WH_Q    ((size_t)2 * DMODEL * DMODEL)
#define WH_OUT  ((size_t)3 * DMODEL * DMODEL)

// ---------------- helpers ----------------
__device__ __forceinline__ uint32_t smem_u32(const void* p) {
    uint32_t a;
    asm("{ .reg .u64 t; cvta.to.shared.u64 t, %1; cvt.u32.u64 %0, t; }" : "=r"(a) : "l"(p));
    return a;
}
__device__ __forceinline__ void cp_async16(uint32_t s, const void* g) {
    asm volatile("cp.async.cg.shared.global [%0], [%1], 16;\n" :: "r"(s), "l"(g));
}
__device__ __forceinline__ void cp_commit() { asm volatile("cp.async.commit_group;\n" ::); }
__device__ __forceinline__ void cp_wait0()  { asm volatile("cp.async.wait_group 0;\n" ::); }
__device__ __forceinline__ void cp_wait1()  { asm volatile("cp.async.wait_group 1;\n" ::); }

// fp16 mma: D(16x8,f32) += A(16x16,f16) * B(16x8,f16)
__device__ __forceinline__ void mma16(float* d, const uint32_t* a, const uint32_t* b) {
    asm volatile(
        "mma.sync.aligned.m16n8k16.row.col.f32.f16.f16.f32 "
        "{%0,%1,%2,%3}, {%4,%5,%6,%7}, {%8,%9}, {%0,%1,%2,%3};\n"
        : "+f"(d[0]), "+f"(d[1]), "+f"(d[2]), "+f"(d[3])
        : "r"(a[0]), "r"(a[1]), "r"(a[2]), "r"(a[3]), "r"(b[0]), "r"(b[1]));
}

// ---------------- one-shot weight transpose+convert: [K][N] f32 -> [N][K] f16 ----------------
__global__ __launch_bounds__(256) void transpose_h(
    const float* __restrict__ in, __half* __restrict__ out, int K, int N)
{
    __shared__ float t[32][33];
    const int tx = threadIdx.x, ty = threadIdx.y;
    const int x  = blockIdx.x * 32 + tx;      // n
    const int y0 = blockIdx.y * 32;           // k
#pragma unroll
    for (int i = ty; i < 32; i += 8)
        t[i][tx] = in[(size_t)(y0 + i) * N + x];
    __syncthreads();
    const int ox  = blockIdx.y * 32 + tx;     // k
    const int oy0 = blockIdx.x * 32;          // n
#pragma unroll
    for (int i = ty; i < 32; i += 8)
        out[(size_t)(oy0 + i) * K + ox] = __float2half_rn(t[tx][i]);
}

// ---------------- mask compaction: deterministic block prefix-sum ----------------
__global__ __launch_bounds__(1024) void compact_kernel(
    const int* __restrict__ mask, int* __restrict__ idx, int* __restrict__ cnt)
{
    __shared__ int wsum[32];
    __shared__ int stotal;
    const int b = blockIdx.x, t = threadIdx.x;
    const int* mb = mask + (size_t)b * NTOK;
    const int base4 = t * 4;
    int m0 = mb[base4 + 0] != 0, m1 = mb[base4 + 1] != 0;
    int m2 = mb[base4 + 2] != 0, m3 = mb[base4 + 3] != 0;
    const int s = m0 + m1 + m2 + m3;
    const int lane = t & 31, w = t >> 5;
    int inc = s;
#pragma unroll
    for (int o = 1; o < 32; o <<= 1) {
        int v = __shfl_up_sync(0xffffffffu, inc, o);
        if (lane >= o) inc += v;
    }
    if (lane == 31) wsum[w] = inc;
    __syncthreads();
    if (w == 0) {
        int v = wsum[lane];
#pragma unroll
        for (int o = 1; o < 32; o <<= 1) {
            int u = __shfl_up_sync(0xffffffffu, v, o);
            if (lane >= o) v += u;
        }
        wsum[lane] = v;
    }
    __syncthreads();
    const int basep = inc - s + (w ? wsum[w - 1] : 0);
    int* ib = idx + (size_t)b * PADK;
    int p = basep;
    if (m0) ib[p++] = base4 + 0;
    if (m1) ib[p++] = base4 + 1;
    if (m2) ib[p++] = base4 + 2;
    if (m3) ib[p++] = base4 + 3;
    if (t == 1023) stotal = basep + s;
    __syncthreads();
    const int total = stotal;
    if (t < NLAT) ib[total + t] = NTOK + t;
    for (int j = total + NLAT + t; j < PADK; j += 1024) ib[j] = NTOK;
    if (t == 0) cnt[b] = total + NLAT;
}

// ---------------- shared LN row body -> fp16 output ----------------
__device__ __forceinline__ void ln_row_h(const float* __restrict__ xr,
                                         const float* __restrict__ gamma,
                                         const float* __restrict__ beta,
                                         __half* __restrict__ outr)
{
    const int t = threadIdx.x;
    float4 v = ((const float4*)xr)[t];
    float s  = v.x + v.y + v.z + v.w;
    float ss = v.x*v.x + v.y*v.y + v.z*v.z + v.w*v.w;
#pragma unroll
    for (int o = 16; o; o >>= 1) {
        s  += __shfl_xor_sync(0xffffffffu, s, o);
        ss += __shfl_xor_sync(0xffffffffu, ss, o);
    }
    __shared__ float rs[8], rss[8];
    if ((t & 31) == 0) { rs[t >> 5] = s; rss[t >> 5] = ss; }
    __syncthreads();
    float sum = 0.f, sq = 0.f;
#pragma unroll
    for (int i = 0; i < 8; i++) { sum += rs[i]; sq += rss[i]; }
    const float mu  = sum * (1.f / DMODEL);
    const float inv = rsqrtf(sq * (1.f / DMODEL) - mu * mu + 1e-5f);
    float4 g  = ((const float4*)gamma)[t];
    float4 bb = ((const float4*)beta)[t];
    float ox = (v.x - mu) * inv * g.x + bb.x;
    float oy = (v.y - mu) * inv * g.y + bb.y;
    float oz = (v.z - mu) * inv * g.z + bb.z;
    float ow = (v.w - mu) * inv * g.w + bb.w;
    __half2* op = (__half2*)(outr + t * 4);
    op[0] = __floats2half2_rn(ox, oy);
    op[1] = __floats2half2_rn(oz, ow);
}

__global__ __launch_bounds__(256) void ln_dense(
    const float* __restrict__ in, const float* __restrict__ gamma,
    const float* __restrict__ beta, __half* __restrict__ out)
{
    const size_t row = blockIdx.x;
    ln_row_h(in + row * DMODEL, gamma, beta, out + row * DMODEL);
}

__global__ __launch_bounds__(256) void ln_gather(
    const float* __restrict__ x, const float* __restrict__ lat,
    const int* __restrict__ idx, const int* __restrict__ cnt,
    const float* __restrict__ g1, const float* __restrict__ b1,
    const float* __restrict__ g2, const float* __restrict__ b2,
    __half* __restrict__ out)
{
    const int b = blockIdx.y;
    const int slot = blockIdx.x;
    const int nk = cnt[b];
    if (slot >= ((nk + 127) & ~127)) return;
    const int g = idx[(size_t)b * PADK + slot];
    const float* src;
    const float *gam, *bet;
    if (g < NTOK) { src = x   + ((size_t)b * NTOK + g) * DMODEL;          gam = g1; bet = b1; }
    else          { src = lat + ((size_t)b * NLAT + (g - NTOK)) * DMODEL; gam = g2; bet = b2; }
    ln_row_h(src, gam, bet, out + ((size_t)b * PADK + slot) * DMODEL);
}

// ---------------- fp16 GEMM geometry ----------------
#define HBK  32                     // K halves per stage
#define HLD  20                     // words per smem row (32 data halves + 8 pad)
#define HA_W (128 * HLD)            // 128-row A stage words (2560)

// ======== kv GEMM: 128x256 CTA tile, 8 warps (2m x 4n), warp 64x64; head-major fp16 OUT ========
#define HB_W   (256 * HLD)
#define HSTG_W (HA_W + HB_W)        // 7680 words
#define KV_SMEM (2 * HSTG_W * 4)    // 61440 B
#define KV_TILES (PADK / 128)       // 33

__global__ __launch_bounds__(256, 1) void gemm_kv_h(
    const __half* __restrict__ lnh, const __half* __restrict__ Bt,
    __half* __restrict__ kvh, const int* __restrict__ cnt)
{
    const int b    = blockIdx.y / KV_TILES;
    const int tile = blockIdx.y - b * KV_TILES;
    const int bm   = tile * 128;
    if (bm >= cnt[b]) return;

    const __half* A = lnh + ((size_t)b * PADK + bm) * DMODEL;
    const int bn = blockIdx.x * 256;

    extern __shared__ uint32_t smw[];
    const int tid = threadIdx.x;
    const int warp = tid >> 5, lane = tid & 31;
    const int wm = (warp >> 2) * 64;
    const int wn = (warp & 3) * 64;
    const int g4 = lane >> 2, t4 = lane & 3;
    const uint32_t s_base = smem_u32(smw);

    float acc[4][8][4];
#pragma unroll
    for (int mi = 0; mi < 4; mi++)
#pragma unroll
        for (int ni = 0; ni < 8; ni++)
#pragma unroll
            for (int c = 0; c < 4; c++) acc[mi][ni][c] = 0.f;

    auto load_stage = [&](int st, int k0) {
        const uint32_t so = (uint32_t)(st * HSTG_W * 4);
#pragma unroll
        for (int j = 0; j < 2; j++) {
            int idx = tid + j * 256, r = idx >> 2, c = idx & 3;
            cp_async16(s_base + so + (uint32_t)((r * HLD + c * 4) * 4),
                       A + (size_t)r * DMODEL + k0 + c * 8);
        }
#pragma unroll
        for (int j = 0; j < 4; j++) {
            int idx = tid + j * 256, r = idx >> 2, c = idx & 3;
            cp_async16(s_base + so + (uint32_t)((HA_W + r * HLD + c * 4) * 4),
                       Bt + (size_t)(bn + r) * DMODEL + k0 + c * 8);
        }
        cp_commit();
    };

    load_stage(0, 0);
    const int KT = DMODEL / HBK;   // 32
    for (int kt = 0; kt < KT; kt++) {
        if (kt + 1 < KT) { load_stage((kt + 1) & 1, (kt + 1) * HBK); cp_wait1(); }
        else             { cp_wait0(); }
        __syncthreads();
        const uint32_t* as = smw + (kt & 1) * HSTG_W;
        const uint32_t* bs = as + HA_W;
#pragma unroll
        for (int kk = 0; kk < 2; kk++) {
            uint32_t af[4][4];
#pragma unroll
            for (int mi = 0; mi < 4; mi++) {
                const uint32_t* ap = as + (wm + mi * 16 + g4) * HLD + kk * 8 + t4;
                af[mi][0] = ap[0];
                af[mi][1] = ap[8 * HLD];
                af[mi][2] = ap[4];
                af[mi][3] = ap[8 * HLD + 4];
            }
            uint32_t bf[8][2];
#pragma unroll
            for (int ni = 0; ni < 8; ni++) {
                const uint32_t* bp = bs + (wn + ni * 8 + g4) * HLD + kk * 8 + t4;
                bf[ni][0] = bp[0];
                bf[ni][1] = bp[4];
            }
#pragma unroll
            for (int mi = 0; mi < 4; mi++)
#pragma unroll
                for (int ni = 0; ni < 8; ni++)
                    mma16(acc[mi][ni], af[mi], bf[ni]);
        }
        __syncthreads();
    }

    // epilogue: head-major scatter. column c -> (isV = c>>10, h = (c&1023)>>6, d = c&63)
    // dst row = [b][h][slot][ isV*64 + d ], row stride 128 halves.
#pragma unroll
    for (int mi = 0; mi < 4; mi++) {
        int r0 = bm + wm + mi * 16 + g4;
#pragma unroll
        for (int ni = 0; ni < 8; ni++) {
            int cc  = bn + wn + ni * 8 + t4 * 2;   // group-of-64 aligned chunk
            int isV = cc >> 10;
            int h   = (cc & 1023) >> 6;
            int d   = (cc & 63) + isV * 64;
            __half* dst = kvh + ((size_t)(b * HEADS + h) * PADK) * 128 + d;
            *(__half2*)(dst + (size_t)r0 * 128)       = __floats2half2_rn(acc[mi][ni][0], acc[mi][ni][1]);
            *(__half2*)(dst + (size_t)(r0 + 8) * 128) = __floats2half2_rn(acc[mi][ni][2], acc[mi][ni][3]);
        }
    }
}

// ======== small GEMM: 64x128 CTA tile, 8 warps (2m x 4n), warp 32x32; K=N=1024, fp32 OUT ========
#define SA_W   (64 * HLD)           // 1280 words
#define SB_W   (128 * HLD)          // 2560 words
#define SSTG_W (SA_W + SB_W)        // 3840 words
#define SG_SMEM (2 * SSTG_W * 4)    // 30720 B

__global__ __launch_bounds__(256) void gemm_h(
    const __half* __restrict__ Ag, const __half* __restrict__ Bt, float* __restrict__ C)
{
    const __half* A = Ag + (size_t)(blockIdx.y * 64) * DMODEL;
    C += (size_t)(blockIdx.y * 64) * DMODEL;
    const int bn = blockIdx.x * 128;

    extern __shared__ uint32_t smw[];
    const int tid = threadIdx.x;
    const int warp = tid >> 5, lane = tid & 31;
    const int wm = (warp >> 2) * 32;
    const int wn = (warp & 3) * 32;
    const int g4 = lane >> 2, t4 = lane & 3;
    const uint32_t s_base = smem_u32(smw);

    float acc[2][4][4];
#pragma unroll
    for (int mi = 0; mi < 2; mi++)
#pragma unroll
        for (int ni = 0; ni < 4; ni++)
#pragma unroll
            for (int c = 0; c < 4; c++) acc[mi][ni][c] = 0.f;

    auto load_stage = [&](int st, int k0) {
        const uint32_t so = (uint32_t)(st * SSTG_W * 4);
        {   // A: 64 rows x 4 chunks = 256 cp
            int r = tid >> 2, c = tid & 3;
            cp_async16(s_base + so + (uint32_t)((r * HLD + c * 4) * 4),
                       A + (size_t)r * DMODEL + k0 + c * 8);
        }
#pragma unroll
        for (int j = 0; j < 2; j++) {   // B: 128 rows x 4 chunks = 512 cp
            int idx = tid + j * 256, r = idx >> 2, c = idx & 3;
            cp_async16(s_base + so + (uint32_t)((SA_W + r * HLD + c * 4) * 4),
                       Bt + (size_t)(bn + r) * DMODEL + k0 + c * 8);
        }
        cp_commit();
    };

    load_stage(0, 0);
    const int KT = DMODEL / HBK;
    for (int kt = 0; kt < KT; kt++) {
        if (kt + 1 < KT) { load_stage((kt + 1) & 1, (kt + 1) * HBK); cp_wait1(); }
        else             { cp_wait0(); }
        __syncthreads();
        const uint32_t* as = smw + (kt & 1) * SSTG_W;
        const uint32_t* bs = as + SA_W;
#pragma unroll
        for (int kk = 0; kk < 2; kk++) {
            uint32_t af[2][4];
#pragma unroll
            for (int mi = 0; mi < 2; mi++) {
                const uint32_t* ap = as + (wm + mi * 16 + g4) * HLD + kk * 8 + t4;
                af[mi][0] = ap[0];
                af[mi][1] = ap[8 * HLD];
                af[mi][2] = ap[4];
                af[mi][3] = ap[8 * HLD + 4];
            }
            uint32_t bf[4][2];
#pragma unroll
            for (int ni = 0; ni < 4; ni++) {
                const uint32_t* bp = bs + (wn + ni * 8 + g4) * HLD + kk * 8 + t4;
                bf[ni][0] = bp[0];
                bf[ni][1] = bp[4];
            }
#pragma unroll
            for (int mi = 0; mi < 2; mi++)
#pragma unroll
                for (int ni = 0; ni < 4; ni++)
                    mma16(acc[mi][ni], af[mi], bf[ni]);
        }
        __syncthreads();
    }

#pragma unroll
    for (int mi = 0; mi < 2; mi++) {
        int r0 = wm + mi * 16 + g4;
#pragma unroll
        for (int ni = 0; ni < 4; ni++) {
            int c0 = bn + wn + ni * 8 + t4 * 2;
            *(float2*)(C + (long long)r0 * DMODEL + c0)       = make_float2(acc[mi][ni][0], acc[mi][ni][1]);
            *(float2*)(C + (long long)(r0 + 8) * DMODEL + c0) = make_float2(acc[mi][ni][2], acc[mi][ni][3]);
        }
    }
}

// ---------------- fp16 mma flash attention, one CTA per (b, h), head-major kv ----------------
#define AW_Q   0
#define AW_K   2304              // 2 stages of 2304
#define AW_V   (2304 * 3)        // 2 stages
#define AW_T   (2304 * 5)        // V transposed [d][key]
#define AW_P   (2304 * 6)        // P fp16 [q][key]
#define AW_PS  (2304 * 7)        // S fp32 [64][68]
#define AW_MK  (AW_PS + 64 * 68)
#define AW_CR  (AW_MK + 64)
#define ATTN_SMEM2 ((AW_CR + 64) * 4)   // 82432 B

__global__ __launch_bounds__(256) void attn_mma(
    const float* __restrict__ qb, const __half* __restrict__ kvh,
    const int* __restrict__ cnt, __half* __restrict__ atth)
{
    extern __shared__ uint32_t aw[];
    __half* Qh = (__half*)(aw + AW_Q);
    __half* Vt = (__half*)(aw + AW_T);
    __half* Ph = (__half*)(aw + AW_P);
    float* Ps = (float*)(aw + AW_PS);
    float* Mk = (float*)(aw + AW_MK);
    float* Cr = (float*)(aw + AW_CR);

    const int tid = threadIdx.x;
    const int w = tid >> 5, lane = tid & 31;
    const int g4 = lane >> 2, t4 = lane & 3;
    const int wm = (w >> 2) * 32, wn = (w & 3) * 16;
    const int b = blockIdx.x >> 4, h = blockIdx.x & 15;
    const int nk = cnt[b];
    const int nch = (nk + 63) >> 6;
    const uint32_t s_base = smem_u32(aw);
    const int q = tid >> 2, sub = tid & 3;

    // Q: 64x64 f32 -> fp16 with 1/8 scale folded in
    {
        const int r = tid >> 2, c0 = (tid & 3) * 16;
        const float* src = qb + ((size_t)(b * NLAT + r)) * DMODEL + h * DH + c0;
        __half2* dst = (__half2*)(Qh + r * 72 + c0);
#pragma unroll
        for (int i = 0; i < 4; i++) {
            float4 v = ((const float4*)src)[i];
            dst[i * 2 + 0] = __floats2half2_rn(v.x * 0.125f, v.y * 0.125f);
            dst[i * 2 + 1] = __floats2half2_rn(v.z * 0.125f, v.w * 0.125f);
        }
    }

    float oa[2][2][4];
#pragma unroll
    for (int mi = 0; mi < 2; mi++)
#pragma unroll
        for (int ni = 0; ni < 2; ni++)
#pragma unroll
            for (int c = 0; c < 4; c++) oa[mi][ni][c] = 0.f;
    float mrun = -1e30f, lsum = 0.f;

    // head-major: contiguous 128 halves per key
    const __half* kb = kvh + ((size_t)(b * HEADS + h) * PADK) * 128;

    auto stage = [&](int ch) {
        const int st = ch & 1, j0 = ch * 64;
#pragma unroll
        for (int j = 0; j < 2; j++) {
            int idx = tid + j * 256, r = idx >> 3, c = idx & 7;
            const __half* s = kb + (size_t)(j0 + r) * 128 + c * 8;
            cp_async16(s_base + (uint32_t)((AW_K + st * 2304 + r * 36 + c * 4) * 4), s);
            cp_async16(s_base + (uint32_t)((AW_V + st * 2304 + r * 36 + c * 4) * 4), s + 64);
        }
        cp_commit();
    };

    stage(0);
    __syncthreads();   // Qh visible to all warps

    for (int ch = 0; ch < nch; ch++) {
        const int st = ch & 1;
        if (ch + 1 < nch) { stage(ch + 1); cp_wait1(); }
        else              { cp_wait0(); }
        __syncthreads();                                  // K/V(st) staged; prev chunk consumers done

        if (tid < 64) Mk[tid] = (ch * 64 + tid < nk) ? 1.f : 0.f;
        // transpose V(st) -> Vt [d][key]
        {
            const int key = tid >> 2, c0 = (tid & 3) * 16;
            const __half* vs = (const __half*)(aw + AW_V + st * 2304) + key * 72 + c0;
#pragma unroll
            for (int i = 0; i < 16; i++)
                Vt[(c0 + i) * 72 + key] = vs[i];
        }

        // S = Q @ K^T
        const uint32_t* Qw = aw + AW_Q;
        const uint32_t* Kw = aw + AW_K + st * 2304;
        float sc[2][2][4];
#pragma unroll
        for (int mi = 0; mi < 2; mi++)
#pragma unroll
            for (int ni = 0; ni < 2; ni++)
#pragma unroll
                for (int c = 0; c < 4; c++) sc[mi][ni][c] = 0.f;
#pragma unroll
        for (int ks = 0; ks < 4; ks++) {
            uint32_t af[2][4];
#pragma unroll
            for (int mi = 0; mi < 2; mi++) {
                const uint32_t* ap = Qw + (wm + mi * 16 + g4) * 36 + ks * 8 + t4;
                af[mi][0] = ap[0];
                af[mi][1] = ap[8 * 36];
                af[mi][2] = ap[4];
                af[mi][3] = ap[8 * 36 + 4];
            }
            uint32_t bf[2][2];
#pragma unroll
            for (int ni = 0; ni < 2; ni++) {
                const uint32_t* bp = Kw + (wn + ni * 8 + g4) * 36 + ks * 8 + t4;
                bf[ni][0] = bp[0];
                bf[ni][1] = bp[4];
            }
#pragma unroll
            for (int mi = 0; mi < 2; mi++)
#pragma unroll
                for (int ni = 0; ni < 2; ni++)
                    mma16(sc[mi][ni], af[mi], bf[ni]);
        }
#pragma unroll
        for (int mi = 0; mi < 2; mi++) {
            int r0 = wm + mi * 16 + g4;
#pragma unroll
            for (int ni = 0; ni < 2; ni++) {
                int c0 = wn + ni * 8 + t4 * 2;
                *(float2*)(Ps + r0 * 68 + c0)       = make_float2(sc[mi][ni][0], sc[mi][ni][1]);
                *(float2*)(Ps + (r0 + 8) * 68 + c0) = make_float2(sc[mi][ni][2], sc[mi][ni][3]);
            }
        }
        __syncthreads();                                  // S + Mk + Vt ready

        // online softmax (proven scalar structure, reading Ps)
        float sreg[16];
#pragma unroll
        for (int jj = 0; jj < 16; jj++) {
            sreg[jj] = Ps[q * 68 + 4 * jj + sub];
            if (!(Mk[4 * jj + sub] > 0.f)) sreg[jj] = -1e30f;
        }
        float mloc = -1e30f;
#pragma unroll
        for (int jj = 0; jj < 16; jj++) mloc = fmaxf(mloc, sreg[jj]);
        mloc = fmaxf(mloc, __shfl_xor_sync(0xffffffffu, mloc, 1));
        mloc = fmaxf(mloc, __shfl_xor_sync(0xffffffffu, mloc, 2));
        float mnew = fmaxf(mrun, mloc);
        float corr = __expf(mrun - mnew);
        float psum = 0.f;
#pragma unroll
        for (int jj = 0; jj < 16; jj++) {
            int j = 4 * jj + sub;
            float p = __expf(sreg[jj] - mnew) * Mk[j];
            psum += p;
            Ph[q * 72 + j] = __float2half_rn(p);
        }
        psum += __shfl_xor_sync(0xffffffffu, psum, 1);
        psum += __shfl_xor_sync(0xffffffffu, psum, 2);
        lsum = lsum * corr + psum;
        if (sub == 0) Cr[q] = corr;
        mrun = mnew;
        __syncthreads();                                  // Ph + Cr ready

        // O = O*corr + P @ V  (A = Ph, B = Vt)
        const uint32_t* Pw = aw + AW_P;
        const uint32_t* Tw = aw + AW_T;
#pragma unroll
        for (int mi = 0; mi < 2; mi++) {
            const float cr0 = Cr[wm + mi * 16 + g4];
            const float cr1 = Cr[wm + mi * 16 + g4 + 8];
#pragma unroll
            for (int ni = 0; ni < 2; ni++) {
                oa[mi][ni][0] *= cr0; oa[mi][ni][1] *= cr0;
                oa[mi][ni][2] *= cr1; oa[mi][ni][3] *= cr1;
            }
        }
#pragma unroll
        for (int ks = 0; ks < 4; ks++) {
            uint32_t af[2][4];
#pragma unroll
            for (int mi = 0; mi < 2; mi++) {
                const uint32_t* ap = Pw + (wm + mi * 16 + g4) * 36 + ks * 8 + t4;
                af[mi][0] = ap[0];
                af[mi][1] = ap[8 * 36];
                af[mi][2] = ap[4];
                af[mi][3] = ap[8 * 36 + 4];
            }
            uint32_t bf[2][2];
#pragma unroll
            for (int ni = 0; ni < 2; ni++) {
                const uint32_t* bp = Tw + (wn + ni * 8 + g4) * 36 + ks * 8 + t4;
                bf[ni][0] = bp[0];
                bf[ni][1] = bp[4];
            }
#pragma unroll
            for (int mi = 0; mi < 2; mi++)
#pragma unroll
                for (int ni = 0; ni < 2; ni++)
                    mma16(oa[mi][ni], af[mi], bf[ni]);
        }
        __syncthreads();                                  // protect Vt/Ph/Kh/Vh for next chunk
    }

    // normalize and store (fp16, feeds out-projection GEMM)
    if (sub == 0) Cr[q] = __fdividef(1.f, lsum);
    __syncthreads();
#pragma unroll
    for (int mi = 0; mi < 2; mi++) {
        int r0 = wm + mi * 16 + g4;
        float rl0 = Cr[r0], rl1 = Cr[r0 + 8];
#pragma unroll
        for (int ni = 0; ni < 2; ni++) {
            int c0 = wn + ni * 8 + t4 * 2;
            *(__half2*)(atth + ((size_t)(b * NLAT + r0)) * DMODEL + h * DH + c0) =
                __floats2half2_rn(oa[mi][ni][0] * rl0, oa[mi][ni][1] * rl0);
            *(__half2*)(atth + ((size_t)(b * NLAT + r0 + 8)) * DMODEL + h * DH + c0) =
                __floats2half2_rn(oa[mi][ni][2] * rl1, oa[mi][ni][3] * rl1);
        }
    }
}

// ---------------- launch ----------------
extern "C" void kernel_launch(void* const* d_in, const int* in_sizes, int n_in,
                              void* d_out, int out_size)
{
    const float* x    = (const float*)d_in[0];
    const float* lat  = (const float*)d_in[1];
    const int*   mask = (const int*)d_in[2];
    const float* g1   = (const float*)d_in[3];
    const float* b1   = (const float*)d_in[4];
    const float* g2   = (const float*)d_in[5];
    const float* b2   = (const float*)d_in[6];
    const float* Wq   = (const float*)d_in[7];
    const float* Wkv  = (const float*)d_in[8];
    const float* Wout = (const float*)d_in[9];
    float* out = (float*)d_out;

    __half *lnhp, *lnlathp, *atthp, *whp, *kvhp;
    float *qp;
    int *idxp, *cntp;
    cudaGetSymbolAddress((void**)&lnhp,    g_lnh);
    cudaGetSymbolAddress((void**)&kvhp,    g_kvh);
    cudaGetSymbolAddress((void**)&lnlathp, g_lnlath);
    cudaGetSymbolAddress((void**)&qp,      g_q);
    cudaGetSymbolAddress((void**)&atthp,   g_atth);
    cudaGetSymbolAddress((void**)&whp,     g_wh);
    cudaGetSymbolAddress((void**)&idxp,    g_idx);
    cudaGetSymbolAddress((void**)&cntp,    g_cnt);

    cudaFuncSetAttribute(gemm_kv_h, cudaFuncAttributeMaxDynamicSharedMemorySize, KV_SMEM);
    cudaFuncSetAttribute(gemm_h,    cudaFuncAttributeMaxDynamicSharedMemorySize, SG_SMEM);
    cudaFuncSetAttribute(attn_mma,  cudaFuncAttributeMaxDynamicSharedMemorySize, ATTN_SMEM2);

    // 0. transpose + fp16-convert weights (one-shot)
    transpose_h<<<dim3(2 * DMODEL / 32, DMODEL / 32), dim3(32, 8)>>>(Wkv,  whp + WH_KV,  DMODEL, 2 * DMODEL);
    transpose_h<<<dim3(DMODEL / 32, DMODEL / 32),     dim3(32, 8)>>>(Wq,   whp + WH_Q,   DMODEL, DMODEL);
    transpose_h<<<dim3(DMODEL / 32, DMODEL / 32),     dim3(32, 8)>>>(Wout, whp + WH_OUT, DMODEL, DMODEL);

    // 1. compact unmasked token indices (+ latents) per batch
    compact_kernel<<<BATCH, 1024>>>(mask, idxp, cntp);

    // 2. LN(latents) dense (for q), fp16
    ln_dense<<<BATCH * NLAT, 256>>>(lat, g2, b2, lnlathp);

    // 3. LN in compacted key order, fp16
    ln_gather<<<dim3(PADK, BATCH), 256>>>(x, lat, idxp, cntp, g1, b1, g2, b2, lnhp);

    // 4. kv = ln_compact @ Wkv   (fp16 mma, head-major fp16 out)
    gemm_kv_h<<<dim3(2 * DMODEL / 256, BATCH * KV_TILES), 256, KV_SMEM>>>(
        lnhp, whp + WH_KV, kvhp, cntp);

    // 5. q = LN(latents) @ Wq  (fp16 mma, fp32 out, 64-row tiles)
    gemm_h<<<dim3(DMODEL / 128, (BATCH * NLAT) / 64), 256, SG_SMEM>>>(
        lnlathp, whp + WH_Q, qp);

    // 6. attention (fp16 mma S and PV, fp32 softmax, streaming kv reads)
    attn_mma<<<BATCH * HEADS, 256, ATTN_SMEM2>>>(qp, kvhp, cntp, atthp);

    // 7. out = att @ Wout  (fp16 mma, fp32 out, 64-row tiles)
    gemm_h<<<dim3(DMODEL / 128, (BATCH * NLAT) / 64), 256, SG_SMEM>>>(
        atthp, whp + WH_OUT, out);
}